// round 3
// baseline (speedup 1.0000x reference)
#include <cuda_runtime.h>
#include <mma.h>
#include <math.h>

using namespace nvcuda;

#define BB 2
#define TT 2048
#define DD 1024
#define HH 16
#define DH 64
#define NREL 7

// Scratch (static device globals — no allocation)
__device__ float g_q[BB*TT*HH*DH];
__device__ float g_k[BB*TT*HH*DH];
__device__ float g_v[BB*TT*HH*DH];
__device__ float g_attn[BB*TT*HH*DH];
__device__ float g_pk[NREL*HH*DH];

// ---------------------------------------------------------------------------
// 3xTF32 tensor-core GEMM: C[M,N] = A[M,K] @ W[K,N] + bias[N]
// BM=BN=128, BK=16, 256 threads (8 warps, 2x4), warp tile 64x32.
// Operands split hi/lo at smem fill: full fp32 accuracy (~1e-7) on tensor pipe.
// ---------------------------------------------------------------------------
#define GS 132   // smem row stride (floats)

__global__ __launch_bounds__(256) void gemm_tf32(
    const float* __restrict__ A, const float* __restrict__ W,
    const float* __restrict__ bias, float* __restrict__ C,
    int M, int N, int K)
{
    __shared__ float Ah[16][GS];   // k-major: Ah[k][m]
    __shared__ float Al[16][GS];
    __shared__ float Bh[16][GS];   // Bh[k][n]
    __shared__ float Bl[16][GS];
    __shared__ float biasS[16][GS];

    const int tid  = threadIdx.x;
    const int warp = tid >> 5;
    const int wm   = (warp & 1) * 64;   // warp M offset in tile
    const int wn   = (warp >> 1) * 32;  // warp N offset in tile
    const int bm   = blockIdx.y * 128;
    const int bn   = blockIdx.x * 128;

    // bias broadcast tile: all 16 rows identical
    #pragma unroll
    for (int it = 0; it < 8; it++) {
        int l = tid + it * 256;          // 0..2047
        int r = l >> 7, c = l & 127;
        biasS[r][c] = bias[bn + c];
    }
    __syncthreads();

    wmma::fragment<wmma::accumulator, 16, 16, 8, float> cfr[4][2];
    #pragma unroll
    for (int i = 0; i < 4; i++)
        #pragma unroll
        for (int j = 0; j < 2; j++)
            wmma::load_matrix_sync(cfr[i][j], &biasS[0][wn + j * 16], GS,
                                   wmma::mem_row_major);
    __syncthreads();

    for (int k0 = 0; k0 < K; k0 += 16) {
        // A tile 128x16 -> k-major smem, hi/lo split
        #pragma unroll
        for (int it = 0; it < 2; it++) {
            int la = tid + it * 256;      // float4 slots
            int row = la >> 2;
            int k4 = (la & 3) << 2;
            float4 v = *(const float4*)(A + (size_t)(bm + row) * K + k0 + k4);
            float vh, vl;
            vh = wmma::__float_to_tf32(v.x); vl = wmma::__float_to_tf32(v.x - vh);
            Ah[k4 + 0][row] = vh; Al[k4 + 0][row] = vl;
            vh = wmma::__float_to_tf32(v.y); vl = wmma::__float_to_tf32(v.y - vh);
            Ah[k4 + 1][row] = vh; Al[k4 + 1][row] = vl;
            vh = wmma::__float_to_tf32(v.z); vl = wmma::__float_to_tf32(v.z - vh);
            Ah[k4 + 2][row] = vh; Al[k4 + 2][row] = vl;
            vh = wmma::__float_to_tf32(v.w); vl = wmma::__float_to_tf32(v.w - vh);
            Ah[k4 + 3][row] = vh; Al[k4 + 3][row] = vl;
        }
        // B tile 16x128 -> smem, hi/lo split
        #pragma unroll
        for (int it = 0; it < 2; it++) {
            int lb = tid + it * 256;
            int kr = lb >> 5;
            int n4 = (lb & 31) << 2;
            float4 v = *(const float4*)(W + (size_t)(k0 + kr) * N + bn + n4);
            float4 h, l;
            h.x = wmma::__float_to_tf32(v.x); l.x = wmma::__float_to_tf32(v.x - h.x);
            h.y = wmma::__float_to_tf32(v.y); l.y = wmma::__float_to_tf32(v.y - h.y);
            h.z = wmma::__float_to_tf32(v.z); l.z = wmma::__float_to_tf32(v.z - h.z);
            h.w = wmma::__float_to_tf32(v.w); l.w = wmma::__float_to_tf32(v.w - h.w);
            *(float4*)(&Bh[kr][n4]) = h;
            *(float4*)(&Bl[kr][n4]) = l;
        }
        __syncthreads();

        #pragma unroll
        for (int kk = 0; kk < 16; kk += 8) {
            wmma::fragment<wmma::matrix_a, 16, 16, 8, wmma::precision::tf32,
                           wmma::col_major> ah[4], al[4];
            wmma::fragment<wmma::matrix_b, 16, 16, 8, wmma::precision::tf32,
                           wmma::row_major> bh[2], bl[2];
            #pragma unroll
            for (int i = 0; i < 4; i++) {
                wmma::load_matrix_sync(ah[i], &Ah[kk][wm + i * 16], GS);
                wmma::load_matrix_sync(al[i], &Al[kk][wm + i * 16], GS);
            }
            #pragma unroll
            for (int j = 0; j < 2; j++) {
                wmma::load_matrix_sync(bh[j], &Bh[kk][wn + j * 16], GS);
                wmma::load_matrix_sync(bl[j], &Bl[kk][wn + j * 16], GS);
            }
            #pragma unroll
            for (int i = 0; i < 4; i++)
                #pragma unroll
                for (int j = 0; j < 2; j++) {
                    wmma::mma_sync(cfr[i][j], ah[i], bh[j], cfr[i][j]);
                    wmma::mma_sync(cfr[i][j], ah[i], bl[j], cfr[i][j]);
                    wmma::mma_sync(cfr[i][j], al[i], bh[j], cfr[i][j]);
                }
        }
        __syncthreads();
    }

    #pragma unroll
    for (int i = 0; i < 4; i++)
        #pragma unroll
        for (int j = 0; j < 2; j++) {
            float* cp = C + (size_t)(bm + wm + i * 16) * N + bn + wn + j * 16;
            wmma::store_matrix_sync(cp, cfr[i][j], N, wmma::mem_row_major);
        }
}

// ---------------------------------------------------------------------------
// pk = pos_emb(7,1024) @ Wk(1024,1024) + bk : init + k-split atomic version
// ---------------------------------------------------------------------------
__global__ void pk_init(const float* __restrict__ bk, float* __restrict__ pk)
{
    int i = blockIdx.x * 256 + threadIdx.x;   // 7168 total
    if (i < NREL * DD) pk[i] = bk[i & (DD - 1)];
}

__global__ __launch_bounds__(256) void pk_gemm_split(
    const float* __restrict__ pos_emb, const float* __restrict__ Wk,
    float* __restrict__ pk)
{
    __shared__ float pe_s[NREL][128];
    const int n  = blockIdx.x * 256 + threadIdx.x;
    const int k0 = blockIdx.y * 128;

    for (int i = threadIdx.x; i < NREL * 128; i += 256) {
        int r = i >> 7, kk = i & 127;
        pe_s[r][kk] = pos_emb[r * DD + k0 + kk];
    }
    __syncthreads();

    float acc[NREL];
    #pragma unroll
    for (int r = 0; r < NREL; r++) acc[r] = 0.f;

    #pragma unroll 4
    for (int kk = 0; kk < 128; kk++) {
        float w = Wk[(size_t)(k0 + kk) * DD + n];
        #pragma unroll
        for (int r = 0; r < NREL; r++) acc[r] += pe_s[r][kk] * w;
    }
    #pragma unroll
    for (int r = 0; r < NREL; r++)
        atomicAdd(&pk[r * DD + n], acc[r]);
}

// ---------------------------------------------------------------------------
// Fused flash attention with TransformerXL relative bias (unchanged).
// ---------------------------------------------------------------------------
#define QS_STRIDE 132
#define KS_STRIDE 68
#define PS_STRIDE 132

__global__ __launch_bounds__(128, 2) void attn_kernel(
    const float* __restrict__ q, const float* __restrict__ k,
    const float* __restrict__ v, const float* __restrict__ pk,
    const float* __restrict__ cbias, const float* __restrict__ rbias,
    float* __restrict__ out)
{
    extern __shared__ float sm[];
    float* Qs     = sm;
    float* Ks     = Qs + 64 * QS_STRIDE;
    float* Vs     = Ks + 64 * KS_STRIDE;
    float* Ps     = Vs + 64 * KS_STRIDE;
    float* smalls = Ps + 64 * PS_STRIDE;
    float* pks    = smalls + 128 * 8;
    float* us     = pks + NREL * 64;
    float* corr   = us + 64;

    const int tid = threadIdx.x;
    const int tx = tid & 7;
    const int ty = tid >> 3;
    const int h = blockIdx.y;
    const int b = blockIdx.z;
    const int q0 = blockIdx.x * 128;

    const float* qb = q + (size_t)b * TT * (HH * DH) + h * DH;
    const float* kb = k + (size_t)b * TT * (HH * DH) + h * DH;
    const float* vb = v + (size_t)b * TT * (HH * DH) + h * DH;

    if (tid < 64) us[tid] = cbias[h * DH + tid];
    for (int i = tid; i < NREL * 64; i += 128) {
        int r = i >> 6, d = i & 63;
        pks[i] = pk[r * DD + h * DH + d];
    }
    __syncthreads();

    #pragma unroll
    for (int it = 0; it < 16; it++) {
        int l = tid + it * 128;
        int row = l >> 4;
        int d4 = (l & 15) << 2;
        float4 vq = *(const float4*)(qb + (size_t)(q0 + row) * (HH * DH) + d4);
        Qs[(d4 + 0) * QS_STRIDE + row] = vq.x + us[d4 + 0];
        Qs[(d4 + 1) * QS_STRIDE + row] = vq.y + us[d4 + 1];
        Qs[(d4 + 2) * QS_STRIDE + row] = vq.z + us[d4 + 2];
        Qs[(d4 + 3) * QS_STRIDE + row] = vq.w + us[d4 + 3];
    }
    if (tid < NREL) {
        float s = 0.f;
        for (int d = 0; d < 64; d++)
            s += (rbias[h * DH + d] - us[d]) * pks[tid * 64 + d];
        corr[tid] = s;
    }
    __syncthreads();

    {
        float accr[NREL];
        #pragma unroll
        for (int r = 0; r < NREL; r++) accr[r] = corr[r];
        for (int d = 0; d < 64; d++) {
            float qv = Qs[d * QS_STRIDE + tid];
            #pragma unroll
            for (int r = 0; r < NREL; r++) accr[r] += qv * pks[r * 64 + d];
        }
        #pragma unroll
        for (int r = 0; r < NREL; r++) smalls[tid * 8 + r] = accr[r];
    }
    __syncthreads();

    float m_i[8], l_i[8], O[8][8];
    #pragma unroll
    for (int i = 0; i < 8; i++) {
        m_i[i] = -1e30f; l_i[i] = 0.f;
        #pragma unroll
        for (int j = 0; j < 8; j++) O[i][j] = 0.f;
    }
    const float scale = 0.125f;

    for (int kt = 0; kt < TT; kt += 64) {
        __syncthreads();
        #pragma unroll
        for (int it = 0; it < 8; it++) {
            int l = tid + it * 128;
            int row = l >> 4;
            int d4 = (l & 15) << 2;
            float4 vk = *(const float4*)(kb + (size_t)(kt + row) * (HH * DH) + d4);
            Ks[(d4 + 0) * KS_STRIDE + row] = vk.x;
            Ks[(d4 + 1) * KS_STRIDE + row] = vk.y;
            Ks[(d4 + 2) * KS_STRIDE + row] = vk.z;
            Ks[(d4 + 3) * KS_STRIDE + row] = vk.w;
            float4 vv = *(const float4*)(vb + (size_t)(kt + row) * (HH * DH) + d4);
            *(float4*)(&Vs[row * KS_STRIDE + d4]) = vv;
        }
        __syncthreads();

        float S[8][8];
        #pragma unroll
        for (int i = 0; i < 8; i++)
            #pragma unroll
            for (int j = 0; j < 8; j++) S[i][j] = 0.f;

        #pragma unroll
        for (int d = 0; d < 64; d++) {
            float a[8], bf[8];
            *(float4*)(a)      = *(float4*)(&Qs[d * QS_STRIDE + ty * 8]);
            *(float4*)(a + 4)  = *(float4*)(&Qs[d * QS_STRIDE + ty * 8 + 4]);
            *(float4*)(bf)     = *(float4*)(&Ks[d * KS_STRIDE + tx * 8]);
            *(float4*)(bf + 4) = *(float4*)(&Ks[d * KS_STRIDE + tx * 8 + 4]);
            #pragma unroll
            for (int i = 0; i < 8; i++)
                #pragma unroll
                for (int j = 0; j < 8; j++)
                    S[i][j] += a[i] * bf[j];
        }

        #pragma unroll
        for (int i = 0; i < 8; i++) {
            int tq = q0 + ty * 8 + i;
            const float* srow = &smalls[(ty * 8 + i) * 8];
            #pragma unroll
            for (int j = 0; j < 8; j++) {
                int tk = kt + tx * 8 + j;
                int dlt = tq - tk;
                dlt = min(3, max(-3, dlt)) + 3;
                S[i][j] = (S[i][j] + srow[dlt]) * scale;
            }
        }

        #pragma unroll
        for (int i = 0; i < 8; i++) {
            float mt = S[i][0];
            #pragma unroll
            for (int j = 1; j < 8; j++) mt = fmaxf(mt, S[i][j]);
            mt = fmaxf(mt, __shfl_xor_sync(0xffffffffu, mt, 1));
            mt = fmaxf(mt, __shfl_xor_sync(0xffffffffu, mt, 2));
            mt = fmaxf(mt, __shfl_xor_sync(0xffffffffu, mt, 4));
            float mnew = fmaxf(m_i[i], mt);
            float c = __expf(m_i[i] - mnew);
            m_i[i] = mnew;
            float ls = 0.f;
            #pragma unroll
            for (int j = 0; j < 8; j++) {
                float p = __expf(S[i][j] - mnew);
                S[i][j] = p;
                ls += p;
            }
            ls += __shfl_xor_sync(0xffffffffu, ls, 1);
            ls += __shfl_xor_sync(0xffffffffu, ls, 2);
            ls += __shfl_xor_sync(0xffffffffu, ls, 4);
            l_i[i] = l_i[i] * c + ls;
            #pragma unroll
            for (int j = 0; j < 8; j++) O[i][j] *= c;
        }

        #pragma unroll
        for (int j = 0; j < 8; j++) {
            float4 p0 = make_float4(S[0][j], S[1][j], S[2][j], S[3][j]);
            float4 p1 = make_float4(S[4][j], S[5][j], S[6][j], S[7][j]);
            *(float4*)(&Ps[(tx * 8 + j) * PS_STRIDE + ty * 8])     = p0;
            *(float4*)(&Ps[(tx * 8 + j) * PS_STRIDE + ty * 8 + 4]) = p1;
        }
        __syncthreads();

        #pragma unroll
        for (int kk = 0; kk < 64; kk++) {
            float a[8], bf[8];
            *(float4*)(a)      = *(float4*)(&Ps[kk * PS_STRIDE + ty * 8]);
            *(float4*)(a + 4)  = *(float4*)(&Ps[kk * PS_STRIDE + ty * 8 + 4]);
            *(float4*)(bf)     = *(float4*)(&Vs[kk * KS_STRIDE + tx * 8]);
            *(float4*)(bf + 4) = *(float4*)(&Vs[kk * KS_STRIDE + tx * 8 + 4]);
            #pragma unroll
            for (int i = 0; i < 8; i++)
                #pragma unroll
                for (int j = 0; j < 8; j++)
                    O[i][j] += a[i] * bf[j];
        }
    }

    #pragma unroll
    for (int i = 0; i < 8; i++) {
        float inv = 1.f / l_i[i];
        int tq = q0 + ty * 8 + i;
        float4 o0 = make_float4(O[i][0] * inv, O[i][1] * inv,
                                O[i][2] * inv, O[i][3] * inv);
        float4 o1 = make_float4(O[i][4] * inv, O[i][5] * inv,
                                O[i][6] * inv, O[i][7] * inv);
        float* op = out + ((size_t)b * TT + tq) * (HH * DH) + h * DH + tx * 8;
        *(float4*)(op)     = o0;
        *(float4*)(op + 4) = o1;
    }
}

// ---------------------------------------------------------------------------
extern "C" void kernel_launch(void* const* d_in, const int* in_sizes, int n_in,
                              void* d_out, int out_size)
{
    const float* query   = (const float*)d_in[0];
    const float* key_    = (const float*)d_in[1];
    const float* value   = (const float*)d_in[2];
    const float* Wq      = (const float*)d_in[3];
    const float* bq      = (const float*)d_in[4];
    const float* Wk      = (const float*)d_in[5];
    const float* bk      = (const float*)d_in[6];
    const float* Wv      = (const float*)d_in[7];
    const float* bv      = (const float*)d_in[8];
    const float* Wo      = (const float*)d_in[9];
    const float* bo      = (const float*)d_in[10];
    const float* cbias   = (const float*)d_in[11];
    const float* rbias   = (const float*)d_in[12];
    const float* pos_emb = (const float*)d_in[13];

    float *q, *k, *v, *attn, *pk;
    cudaGetSymbolAddress((void**)&q, g_q);
    cudaGetSymbolAddress((void**)&k, g_k);
    cudaGetSymbolAddress((void**)&v, g_v);
    cudaGetSymbolAddress((void**)&attn, g_attn);
    cudaGetSymbolAddress((void**)&pk, g_pk);

    const int M = BB * TT;     // 4096
    const int N = HH * DH;     // 1024
    const int K = DD;          // 1024

    dim3 gg(N / 128, M / 128);  // (8, 32)
    gemm_tf32<<<gg, 256>>>(query, Wq, bq, q, M, N, K);
    gemm_tf32<<<gg, 256>>>(key_,  Wk, bk, k, M, N, K);
    gemm_tf32<<<gg, 256>>>(value, Wv, bv, v, M, N, K);

    pk_init<<<(NREL * DD + 255) / 256, 256>>>(bk, pk);
    pk_gemm_split<<<dim3(DD / 256, DD / 128), 256>>>(pos_emb, Wk, pk);

    // fused attention
    size_t smem = (64 * QS_STRIDE + 64 * KS_STRIDE + 64 * KS_STRIDE +
                   64 * PS_STRIDE + 128 * 8 + NREL * 64 + 64 + 8) * sizeof(float);
    cudaFuncSetAttribute(attn_kernel,
                         cudaFuncAttributeMaxDynamicSharedMemorySize, (int)smem);
    attn_kernel<<<dim3(TT / 128, HH, BB), 128, smem>>>(q, k, v, pk, cbias, rbias, attn);

    // output projection -> d_out
    gemm_tf32<<<gg, 256>>>(attn, Wo, bo, (float*)d_out, M, N, K);
}

// round 4
// speedup vs baseline: 1.3129x; 1.3129x over previous
#include <cuda_runtime.h>
#include <math.h>
#include <stdint.h>

#define BB 2
#define TT 2048
#define DD 1024
#define HH 16
#define DH 64
#define NREL 7

// Scratch (static device globals — no allocation)
__device__ float g_q[BB*TT*HH*DH];
__device__ float g_k[BB*TT*HH*DH];
__device__ float g_v[BB*TT*HH*DH];
__device__ float g_attn[BB*TT*HH*DH];
__device__ float g_pk[NREL*HH*DH];

// ---------------------------------------------------------------------------
// helpers: cp.async, tf32 split, mma
// ---------------------------------------------------------------------------
__device__ __forceinline__ void cp16(void* smem, const void* gmem) {
    uint32_t s = (uint32_t)__cvta_generic_to_shared(smem);
    asm volatile("cp.async.ca.shared.global [%0], [%1], 16;\n" :: "r"(s), "l"(gmem));
}
__device__ __forceinline__ void cp_commit() {
    asm volatile("cp.async.commit_group;\n");
}
__device__ __forceinline__ void cp_wait1() {
    asm volatile("cp.async.wait_group 1;\n");
}

__device__ __forceinline__ void split_tf32(float x, uint32_t& hi, uint32_t& lo) {
    uint32_t h;
    asm("cvt.rna.tf32.f32 %0, %1;" : "=r"(h) : "f"(x));
    float lf = x - __uint_as_float(h);
    uint32_t l;
    asm("cvt.rna.tf32.f32 %0, %1;" : "=r"(l) : "f"(lf));
    hi = h; lo = l;
}

__device__ __forceinline__ void mma_tf32(float* c, const uint32_t* a,
                                         uint32_t b0, uint32_t b1) {
    asm volatile(
        "mma.sync.aligned.m16n8k8.row.col.f32.tf32.tf32.f32 "
        "{%0,%1,%2,%3}, {%4,%5,%6,%7}, {%8,%9}, {%0,%1,%2,%3};"
        : "+f"(c[0]), "+f"(c[1]), "+f"(c[2]), "+f"(c[3])
        : "r"(a[0]), "r"(a[1]), "r"(a[2]), "r"(a[3]), "r"(b0), "r"(b1));
}

// ---------------------------------------------------------------------------
// 3xTF32 tensor-core GEMM: C[M,N] = A[M,K] @ W[K,N] + bias[N]
// BM=64, BN=128, BK=16, 256 threads (8 warps, 2x4), warp tile 32x32.
// Raw fp32 in smem (cp.async 3-stage); hi/lo split done in registers.
// ---------------------------------------------------------------------------
#define ASTRIDE 20
#define BSTRIDE 136

__global__ __launch_bounds__(256, 2) void gemm_tf32(
    const float* __restrict__ A, const float* __restrict__ W,
    const float* __restrict__ bias, float* __restrict__ C,
    int M, int N, int K)
{
    __shared__ float As[3][64][ASTRIDE];    // m-major raw fp32
    __shared__ float Bs[3][16][BSTRIDE];    // k-major raw fp32

    const int tid  = threadIdx.x;
    const int warp = tid >> 5;
    const int lane = tid & 31;
    const int g    = lane >> 2;      // 0..7
    const int tg   = lane & 3;       // 0..3
    const int wm   = (warp & 1) * 32;
    const int wn   = (warp >> 1) * 32;
    const int bm   = blockIdx.y * 64;
    const int bn   = blockIdx.x * 128;

    // A tile fill: 64 rows x 16 -> 256 float4, one per thread
    const int a_row = tid >> 2;
    const int a_c4  = (tid & 3) << 2;
    const float* a_src = A + (size_t)(bm + a_row) * K + a_c4;

    // B tile fill: 16 rows x 128 -> 512 float4, two per thread
    const int b_row0 = tid >> 5;           // 0..7
    const int b_n4   = (tid & 31) << 2;
    const float* b_src = W + (size_t)b_row0 * N + bn + b_n4;

    const int NIT = K >> 4;  // 64

    // prologue: stages 0,1
    #pragma unroll
    for (int s = 0; s < 2; s++) {
        cp16(&As[s][a_row][a_c4], a_src + s * 16);
        cp16(&Bs[s][b_row0][b_n4],     b_src + (size_t)(s * 16) * N);
        cp16(&Bs[s][b_row0 + 8][b_n4], b_src + (size_t)(s * 16 + 8) * N);
        cp_commit();
    }

    float acc[2][4][4];
    #pragma unroll
    for (int i = 0; i < 2; i++)
        #pragma unroll
        for (int j = 0; j < 4; j++)
            #pragma unroll
            for (int r = 0; r < 4; r++) acc[i][j][r] = 0.f;

    for (int it = 0; it < NIT; it++) {
        const int s = it % 3;
        cp_wait1();
        __syncthreads();

        // issue stage it+2
        if (it + 2 < NIT) {
            const int sn = (it + 2) % 3;
            const int k0 = (it + 2) * 16;
            cp16(&As[sn][a_row][a_c4], a_src + k0);
            cp16(&Bs[sn][b_row0][b_n4],     b_src + (size_t)k0 * N);
            cp16(&Bs[sn][b_row0 + 8][b_n4], b_src + (size_t)(k0 + 8) * N);
        }
        cp_commit();

        #pragma unroll
        for (int k8 = 0; k8 < 2; k8++) {
            const int kc = k8 * 8;
            // A fragments (2 m-tiles), split hi/lo in regs
            uint32_t ah[2][4], al[2][4];
            #pragma unroll
            for (int i = 0; i < 2; i++) {
                const int r0 = wm + i * 16 + g;
                split_tf32(As[s][r0][kc + tg],          ah[i][0], al[i][0]);
                split_tf32(As[s][r0 + 8][kc + tg],      ah[i][1], al[i][1]);
                split_tf32(As[s][r0][kc + tg + 4],      ah[i][2], al[i][2]);
                split_tf32(As[s][r0 + 8][kc + tg + 4],  ah[i][3], al[i][3]);
            }
            // B fragments (4 n-tiles), convert on the fly
            #pragma unroll
            for (int j = 0; j < 4; j++) {
                const int nc = wn + j * 8 + g;
                uint32_t bh0, bl0, bh1, bl1;
                split_tf32(Bs[s][kc + tg][nc],     bh0, bl0);
                split_tf32(Bs[s][kc + tg + 4][nc], bh1, bl1);
                #pragma unroll
                for (int i = 0; i < 2; i++) {
                    mma_tf32(acc[i][j], ah[i], bh0, bh1);
                    mma_tf32(acc[i][j], ah[i], bl0, bl1);
                    mma_tf32(acc[i][j], al[i], bh0, bh1);
                }
            }
        }
        __syncthreads();
    }

    // epilogue: bias + store
    #pragma unroll
    for (int j = 0; j < 4; j++) {
        const int col = bn + wn + j * 8 + 2 * tg;
        const float bv0 = bias[col];
        const float bv1 = bias[col + 1];
        #pragma unroll
        for (int i = 0; i < 2; i++) {
            const int row0 = bm + wm + i * 16 + g;
            float2 v0 = make_float2(acc[i][j][0] + bv0, acc[i][j][1] + bv1);
            float2 v1 = make_float2(acc[i][j][2] + bv0, acc[i][j][3] + bv1);
            *(float2*)(C + (size_t)row0 * N + col)       = v0;
            *(float2*)(C + (size_t)(row0 + 8) * N + col) = v1;
        }
    }
}

// ---------------------------------------------------------------------------
// pk = pos_emb(7,1024) @ Wk(1024,1024) + bk : init + k-split atomic version
// ---------------------------------------------------------------------------
__global__ void pk_init(const float* __restrict__ bk, float* __restrict__ pk)
{
    int i = blockIdx.x * 256 + threadIdx.x;
    if (i < NREL * DD) pk[i] = bk[i & (DD - 1)];
}

__global__ __launch_bounds__(256) void pk_gemm_split(
    const float* __restrict__ pos_emb, const float* __restrict__ Wk,
    float* __restrict__ pk)
{
    __shared__ float pe_s[NREL][128];
    const int n  = blockIdx.x * 256 + threadIdx.x;
    const int k0 = blockIdx.y * 128;

    for (int i = threadIdx.x; i < NREL * 128; i += 256) {
        int r = i >> 7, kk = i & 127;
        pe_s[r][kk] = pos_emb[r * DD + k0 + kk];
    }
    __syncthreads();

    float acc[NREL];
    #pragma unroll
    for (int r = 0; r < NREL; r++) acc[r] = 0.f;

    #pragma unroll 4
    for (int kk = 0; kk < 128; kk++) {
        float w = Wk[(size_t)(k0 + kk) * DD + n];
        #pragma unroll
        for (int r = 0; r < NREL; r++) acc[r] += pe_s[r][kk] * w;
    }
    #pragma unroll
    for (int r = 0; r < NREL; r++)
        atomicAdd(&pk[r * DD + n], acc[r]);
}

// ---------------------------------------------------------------------------
// Fused flash attention with TransformerXL relative bias (proven R2 version).
// ---------------------------------------------------------------------------
#define QS_STRIDE 132
#define KS_STRIDE 68
#define PS_STRIDE 132

__global__ __launch_bounds__(128, 2) void attn_kernel(
    const float* __restrict__ q, const float* __restrict__ k,
    const float* __restrict__ v, const float* __restrict__ pk,
    const float* __restrict__ cbias, const float* __restrict__ rbias,
    float* __restrict__ out)
{
    extern __shared__ float sm[];
    float* Qs     = sm;
    float* Ks     = Qs + 64 * QS_STRIDE;
    float* Vs     = Ks + 64 * KS_STRIDE;
    float* Ps     = Vs + 64 * KS_STRIDE;
    float* smalls = Ps + 64 * PS_STRIDE;
    float* pks    = smalls + 128 * 8;
    float* us     = pks + NREL * 64;
    float* corr   = us + 64;

    const int tid = threadIdx.x;
    const int tx = tid & 7;
    const int ty = tid >> 3;
    const int h = blockIdx.y;
    const int b = blockIdx.z;
    const int q0 = blockIdx.x * 128;

    const float* qb = q + (size_t)b * TT * (HH * DH) + h * DH;
    const float* kb = k + (size_t)b * TT * (HH * DH) + h * DH;
    const float* vb = v + (size_t)b * TT * (HH * DH) + h * DH;

    if (tid < 64) us[tid] = cbias[h * DH + tid];
    for (int i = tid; i < NREL * 64; i += 128) {
        int r = i >> 6, d = i & 63;
        pks[i] = pk[r * DD + h * DH + d];
    }
    __syncthreads();

    #pragma unroll
    for (int it = 0; it < 16; it++) {
        int l = tid + it * 128;
        int row = l >> 4;
        int d4 = (l & 15) << 2;
        float4 vq = *(const float4*)(qb + (size_t)(q0 + row) * (HH * DH) + d4);
        Qs[(d4 + 0) * QS_STRIDE + row] = vq.x + us[d4 + 0];
        Qs[(d4 + 1) * QS_STRIDE + row] = vq.y + us[d4 + 1];
        Qs[(d4 + 2) * QS_STRIDE + row] = vq.z + us[d4 + 2];
        Qs[(d4 + 3) * QS_STRIDE + row] = vq.w + us[d4 + 3];
    }
    if (tid < NREL) {
        float s = 0.f;
        for (int d = 0; d < 64; d++)
            s += (rbias[h * DH + d] - us[d]) * pks[tid * 64 + d];
        corr[tid] = s;
    }
    __syncthreads();

    {
        float accr[NREL];
        #pragma unroll
        for (int r = 0; r < NREL; r++) accr[r] = corr[r];
        for (int d = 0; d < 64; d++) {
            float qv = Qs[d * QS_STRIDE + tid];
            #pragma unroll
            for (int r = 0; r < NREL; r++) accr[r] += qv * pks[r * 64 + d];
        }
        #pragma unroll
        for (int r = 0; r < NREL; r++) smalls[tid * 8 + r] = accr[r];
    }
    __syncthreads();

    float m_i[8], l_i[8], O[8][8];
    #pragma unroll
    for (int i = 0; i < 8; i++) {
        m_i[i] = -1e30f; l_i[i] = 0.f;
        #pragma unroll
        for (int j = 0; j < 8; j++) O[i][j] = 0.f;
    }
    const float scale = 0.125f;

    for (int kt = 0; kt < TT; kt += 64) {
        __syncthreads();
        #pragma unroll
        for (int it = 0; it < 8; it++) {
            int l = tid + it * 128;
            int row = l >> 4;
            int d4 = (l & 15) << 2;
            float4 vk = *(const float4*)(kb + (size_t)(kt + row) * (HH * DH) + d4);
            Ks[(d4 + 0) * KS_STRIDE + row] = vk.x;
            Ks[(d4 + 1) * KS_STRIDE + row] = vk.y;
            Ks[(d4 + 2) * KS_STRIDE + row] = vk.z;
            Ks[(d4 + 3) * KS_STRIDE + row] = vk.w;
            float4 vv = *(const float4*)(vb + (size_t)(kt + row) * (HH * DH) + d4);
            *(float4*)(&Vs[row * KS_STRIDE + d4]) = vv;
        }
        __syncthreads();

        float S[8][8];
        #pragma unroll
        for (int i = 0; i < 8; i++)
            #pragma unroll
            for (int j = 0; j < 8; j++) S[i][j] = 0.f;

        #pragma unroll
        for (int d = 0; d < 64; d++) {
            float a[8], bf[8];
            *(float4*)(a)      = *(float4*)(&Qs[d * QS_STRIDE + ty * 8]);
            *(float4*)(a + 4)  = *(float4*)(&Qs[d * QS_STRIDE + ty * 8 + 4]);
            *(float4*)(bf)     = *(float4*)(&Ks[d * KS_STRIDE + tx * 8]);
            *(float4*)(bf + 4) = *(float4*)(&Ks[d * KS_STRIDE + tx * 8 + 4]);
            #pragma unroll
            for (int i = 0; i < 8; i++)
                #pragma unroll
                for (int j = 0; j < 8; j++)
                    S[i][j] += a[i] * bf[j];
        }

        #pragma unroll
        for (int i = 0; i < 8; i++) {
            int tq = q0 + ty * 8 + i;
            const float* srow = &smalls[(ty * 8 + i) * 8];
            #pragma unroll
            for (int j = 0; j < 8; j++) {
                int tk = kt + tx * 8 + j;
                int dlt = tq - tk;
                dlt = min(3, max(-3, dlt)) + 3;
                S[i][j] = (S[i][j] + srow[dlt]) * scale;
            }
        }

        #pragma unroll
        for (int i = 0; i < 8; i++) {
            float mt = S[i][0];
            #pragma unroll
            for (int j = 1; j < 8; j++) mt = fmaxf(mt, S[i][j]);
            mt = fmaxf(mt, __shfl_xor_sync(0xffffffffu, mt, 1));
            mt = fmaxf(mt, __shfl_xor_sync(0xffffffffu, mt, 2));
            mt = fmaxf(mt, __shfl_xor_sync(0xffffffffu, mt, 4));
            float mnew = fmaxf(m_i[i], mt);
            float c = __expf(m_i[i] - mnew);
            m_i[i] = mnew;
            float ls = 0.f;
            #pragma unroll
            for (int j = 0; j < 8; j++) {
                float p = __expf(S[i][j] - mnew);
                S[i][j] = p;
                ls += p;
            }
            ls += __shfl_xor_sync(0xffffffffu, ls, 1);
            ls += __shfl_xor_sync(0xffffffffu, ls, 2);
            ls += __shfl_xor_sync(0xffffffffu, ls, 4);
            l_i[i] = l_i[i] * c + ls;
            #pragma unroll
            for (int j = 0; j < 8; j++) O[i][j] *= c;
        }

        #pragma unroll
        for (int j = 0; j < 8; j++) {
            float4 p0 = make_float4(S[0][j], S[1][j], S[2][j], S[3][j]);
            float4 p1 = make_float4(S[4][j], S[5][j], S[6][j], S[7][j]);
            *(float4*)(&Ps[(tx * 8 + j) * PS_STRIDE + ty * 8])     = p0;
            *(float4*)(&Ps[(tx * 8 + j) * PS_STRIDE + ty * 8 + 4]) = p1;
        }
        __syncthreads();

        #pragma unroll
        for (int kk = 0; kk < 64; kk++) {
            float a[8], bf[8];
            *(float4*)(a)      = *(float4*)(&Ps[kk * PS_STRIDE + ty * 8]);
            *(float4*)(a + 4)  = *(float4*)(&Ps[kk * PS_STRIDE + ty * 8 + 4]);
            *(float4*)(bf)     = *(float4*)(&Vs[kk * KS_STRIDE + tx * 8]);
            *(float4*)(bf + 4) = *(float4*)(&Vs[kk * KS_STRIDE + tx * 8 + 4]);
            #pragma unroll
            for (int i = 0; i < 8; i++)
                #pragma unroll
                for (int j = 0; j < 8; j++)
                    O[i][j] += a[i] * bf[j];
        }
    }

    #pragma unroll
    for (int i = 0; i < 8; i++) {
        float inv = 1.f / l_i[i];
        int tq = q0 + ty * 8 + i;
        float4 o0 = make_float4(O[i][0] * inv, O[i][1] * inv,
                                O[i][2] * inv, O[i][3] * inv);
        float4 o1 = make_float4(O[i][4] * inv, O[i][5] * inv,
                                O[i][6] * inv, O[i][7] * inv);
        float* op = out + ((size_t)b * TT + tq) * (HH * DH) + h * DH + tx * 8;
        *(float4*)(op)     = o0;
        *(float4*)(op + 4) = o1;
    }
}

// ---------------------------------------------------------------------------
extern "C" void kernel_launch(void* const* d_in, const int* in_sizes, int n_in,
                              void* d_out, int out_size)
{
    const float* query   = (const float*)d_in[0];
    const float* key_    = (const float*)d_in[1];
    const float* value   = (const float*)d_in[2];
    const float* Wq      = (const float*)d_in[3];
    const float* bq      = (const float*)d_in[4];
    const float* Wk      = (const float*)d_in[5];
    const float* bk      = (const float*)d_in[6];
    const float* Wv      = (const float*)d_in[7];
    const float* bv      = (const float*)d_in[8];
    const float* Wo      = (const float*)d_in[9];
    const float* bo      = (const float*)d_in[10];
    const float* cbias   = (const float*)d_in[11];
    const float* rbias   = (const float*)d_in[12];
    const float* pos_emb = (const float*)d_in[13];

    float *q, *k, *v, *attn, *pk;
    cudaGetSymbolAddress((void**)&q, g_q);
    cudaGetSymbolAddress((void**)&k, g_k);
    cudaGetSymbolAddress((void**)&v, g_v);
    cudaGetSymbolAddress((void**)&attn, g_attn);
    cudaGetSymbolAddress((void**)&pk, g_pk);

    const int M = BB * TT;     // 4096
    const int N = HH * DH;     // 1024
    const int K = DD;          // 1024

    dim3 gg(N / 128, M / 64);  // (8, 64)
    gemm_tf32<<<gg, 256>>>(query, Wq, bq, q, M, N, K);
    gemm_tf32<<<gg, 256>>>(key_,  Wk, bk, k, M, N, K);
    gemm_tf32<<<gg, 256>>>(value, Wv, bv, v, M, N, K);

    pk_init<<<(NREL * DD + 255) / 256, 256>>>(bk, pk);
    pk_gemm_split<<<dim3(DD / 256, DD / 128), 256>>>(pos_emb, Wk, pk);

    // fused attention
    size_t smem = (64 * QS_STRIDE + 64 * KS_STRIDE + 64 * KS_STRIDE +
                   64 * PS_STRIDE + 128 * 8 + NREL * 64 + 64 + 8) * sizeof(float);
    cudaFuncSetAttribute(attn_kernel,
                         cudaFuncAttributeMaxDynamicSharedMemorySize, (int)smem);
    attn_kernel<<<dim3(TT / 128, HH, BB), 128, smem>>>(q, k, v, pk, cbias, rbias, attn);

    // output projection -> d_out
    gemm_tf32<<<gg, 256>>>(attn, Wo, bo, (float*)d_out, M, N, K);
}

// round 5
// speedup vs baseline: 3.2482x; 2.4741x over previous
#include <cuda_runtime.h>
#include <cuda_bf16.h>
#include <math.h>
#include <stdint.h>

#define BB 2
#define TT 2048
#define DD 1024
#define HH 16
#define DH 64
#define NREL 7

// Scratch (static device globals — no allocation)
__device__ float g_q[BB*TT*HH*DH];
__device__ float g_k[BB*TT*HH*DH];
__device__ float g_v[BB*TT*HH*DH];
__device__ float g_attn[BB*TT*HH*DH];
__device__ float g_pk[NREL*HH*DH];

// ---------------------------------------------------------------------------
// helpers
// ---------------------------------------------------------------------------
__device__ __forceinline__ void cp16(void* smem, const void* gmem) {
    uint32_t s = (uint32_t)__cvta_generic_to_shared(smem);
    asm volatile("cp.async.ca.shared.global [%0], [%1], 16;\n" :: "r"(s), "l"(gmem));
}
__device__ __forceinline__ void cp_commit() {
    asm volatile("cp.async.commit_group;\n");
}
__device__ __forceinline__ void cp_wait1() {
    asm volatile("cp.async.wait_group 1;\n");
}

__device__ __forceinline__ void split_tf32(float x, uint32_t& hi, uint32_t& lo) {
    uint32_t h;
    asm("cvt.rna.tf32.f32 %0, %1;" : "=r"(h) : "f"(x));
    float lf = x - __uint_as_float(h);
    uint32_t l;
    asm("cvt.rna.tf32.f32 %0, %1;" : "=r"(l) : "f"(lf));
    hi = h; lo = l;
}

__device__ __forceinline__ void mma_tf32(float* c, const uint32_t* a,
                                         uint32_t b0, uint32_t b1) {
    asm volatile(
        "mma.sync.aligned.m16n8k8.row.col.f32.tf32.tf32.f32 "
        "{%0,%1,%2,%3}, {%4,%5,%6,%7}, {%8,%9}, {%0,%1,%2,%3};"
        : "+f"(c[0]), "+f"(c[1]), "+f"(c[2]), "+f"(c[3])
        : "r"(a[0]), "r"(a[1]), "r"(a[2]), "r"(a[3]), "r"(b0), "r"(b1));
}

__device__ __forceinline__ void mma_bf16(float* c, const uint32_t* a,
                                         uint32_t b0, uint32_t b1) {
    asm volatile(
        "mma.sync.aligned.m16n8k16.row.col.f32.bf16.bf16.f32 "
        "{%0,%1,%2,%3}, {%4,%5,%6,%7}, {%8,%9}, {%0,%1,%2,%3};"
        : "+f"(c[0]), "+f"(c[1]), "+f"(c[2]), "+f"(c[3])
        : "r"(a[0]), "r"(a[1]), "r"(a[2]), "r"(a[3]), "r"(b0), "r"(b1));
}

__device__ __forceinline__ void ldsm_x2_t(uint32_t& r0, uint32_t& r1, uint32_t addr) {
    asm volatile("ldmatrix.sync.aligned.m8n8.x2.trans.shared.b16 {%0,%1}, [%2];"
                 : "=r"(r0), "=r"(r1) : "r"(addr));
}

// pack two floats into bf16x2 hi word + bf16x2 residual word
__device__ __forceinline__ void split2_bf16(float x0, float x1,
                                            uint32_t& hi, uint32_t& lo) {
    __nv_bfloat16 h0 = __float2bfloat16_rn(x0);
    __nv_bfloat16 h1 = __float2bfloat16_rn(x1);
    float r0 = x0 - __bfloat162float(h0);
    float r1 = x1 - __bfloat162float(h1);
    __nv_bfloat162 H = __halves2bfloat162(h0, h1);
    __nv_bfloat162 L = __halves2bfloat162(__float2bfloat16_rn(r0),
                                          __float2bfloat16_rn(r1));
    hi = *(uint32_t*)&H;
    lo = *(uint32_t*)&L;
}

// ---------------------------------------------------------------------------
// 3xTF32 tensor-core GEMM (unchanged from R4): C = A @ W + bias
// ---------------------------------------------------------------------------
#define ASTRIDE 20
#define BSTRIDE 136

__global__ __launch_bounds__(256, 2) void gemm_tf32(
    const float* __restrict__ A, const float* __restrict__ W,
    const float* __restrict__ bias, float* __restrict__ C,
    int M, int N, int K)
{
    __shared__ float As[3][64][ASTRIDE];
    __shared__ float Bs[3][16][BSTRIDE];

    const int tid  = threadIdx.x;
    const int warp = tid >> 5;
    const int lane = tid & 31;
    const int g    = lane >> 2;
    const int tg   = lane & 3;
    const int wm   = (warp & 1) * 32;
    const int wn   = (warp >> 1) * 32;
    const int bm   = blockIdx.y * 64;
    const int bn   = blockIdx.x * 128;

    const int a_row = tid >> 2;
    const int a_c4  = (tid & 3) << 2;
    const float* a_src = A + (size_t)(bm + a_row) * K + a_c4;

    const int b_row0 = tid >> 5;
    const int b_n4   = (tid & 31) << 2;
    const float* b_src = W + (size_t)b_row0 * N + bn + b_n4;

    const int NIT = K >> 4;

    #pragma unroll
    for (int s = 0; s < 2; s++) {
        cp16(&As[s][a_row][a_c4], a_src + s * 16);
        cp16(&Bs[s][b_row0][b_n4],     b_src + (size_t)(s * 16) * N);
        cp16(&Bs[s][b_row0 + 8][b_n4], b_src + (size_t)(s * 16 + 8) * N);
        cp_commit();
    }

    float acc[2][4][4];
    #pragma unroll
    for (int i = 0; i < 2; i++)
        #pragma unroll
        for (int j = 0; j < 4; j++)
            #pragma unroll
            for (int r = 0; r < 4; r++) acc[i][j][r] = 0.f;

    for (int it = 0; it < NIT; it++) {
        const int s = it % 3;
        cp_wait1();
        __syncthreads();

        if (it + 2 < NIT) {
            const int sn = (it + 2) % 3;
            const int k0 = (it + 2) * 16;
            cp16(&As[sn][a_row][a_c4], a_src + k0);
            cp16(&Bs[sn][b_row0][b_n4],     b_src + (size_t)k0 * N);
            cp16(&Bs[sn][b_row0 + 8][b_n4], b_src + (size_t)(k0 + 8) * N);
        }
        cp_commit();

        #pragma unroll
        for (int k8 = 0; k8 < 2; k8++) {
            const int kc = k8 * 8;
            uint32_t ah[2][4], al[2][4];
            #pragma unroll
            for (int i = 0; i < 2; i++) {
                const int r0 = wm + i * 16 + g;
                split_tf32(As[s][r0][kc + tg],          ah[i][0], al[i][0]);
                split_tf32(As[s][r0 + 8][kc + tg],      ah[i][1], al[i][1]);
                split_tf32(As[s][r0][kc + tg + 4],      ah[i][2], al[i][2]);
                split_tf32(As[s][r0 + 8][kc + tg + 4],  ah[i][3], al[i][3]);
            }
            #pragma unroll
            for (int j = 0; j < 4; j++) {
                const int nc = wn + j * 8 + g;
                uint32_t bh0, bl0, bh1, bl1;
                split_tf32(Bs[s][kc + tg][nc],     bh0, bl0);
                split_tf32(Bs[s][kc + tg + 4][nc], bh1, bl1);
                #pragma unroll
                for (int i = 0; i < 2; i++) {
                    mma_tf32(acc[i][j], ah[i], bh0, bh1);
                    mma_tf32(acc[i][j], ah[i], bl0, bl1);
                    mma_tf32(acc[i][j], al[i], bh0, bh1);
                }
            }
        }
        __syncthreads();
    }

    #pragma unroll
    for (int j = 0; j < 4; j++) {
        const int col = bn + wn + j * 8 + 2 * tg;
        const float bv0 = bias[col];
        const float bv1 = bias[col + 1];
        #pragma unroll
        for (int i = 0; i < 2; i++) {
            const int row0 = bm + wm + i * 16 + g;
            float2 v0 = make_float2(acc[i][j][0] + bv0, acc[i][j][1] + bv1);
            float2 v1 = make_float2(acc[i][j][2] + bv0, acc[i][j][3] + bv1);
            *(float2*)(C + (size_t)row0 * N + col)       = v0;
            *(float2*)(C + (size_t)(row0 + 8) * N + col) = v1;
        }
    }
}

// ---------------------------------------------------------------------------
// pk path (unchanged)
// ---------------------------------------------------------------------------
__global__ void pk_init(const float* __restrict__ bk, float* __restrict__ pk)
{
    int i = blockIdx.x * 256 + threadIdx.x;
    if (i < NREL * DD) pk[i] = bk[i & (DD - 1)];
}

__global__ __launch_bounds__(256) void pk_gemm_split(
    const float* __restrict__ pos_emb, const float* __restrict__ Wk,
    float* __restrict__ pk)
{
    __shared__ float pe_s[NREL][128];
    const int n  = blockIdx.x * 256 + threadIdx.x;
    const int k0 = blockIdx.y * 128;

    for (int i = threadIdx.x; i < NREL * 128; i += 256) {
        int r = i >> 7, kk = i & 127;
        pe_s[r][kk] = pos_emb[r * DD + k0 + kk];
    }
    __syncthreads();

    float acc[NREL];
    #pragma unroll
    for (int r = 0; r < NREL; r++) acc[r] = 0.f;

    #pragma unroll 4
    for (int kk = 0; kk < 128; kk++) {
        float w = Wk[(size_t)(k0 + kk) * DD + n];
        #pragma unroll
        for (int r = 0; r < NREL; r++) acc[r] += pe_s[r][kk] * w;
    }
    #pragma unroll
    for (int r = 0; r < NREL; r++)
        atomicAdd(&pk[r * DD + n], acc[r]);
}

// ---------------------------------------------------------------------------
// Tensor-core flash attention with TransformerXL relative bias.
// 64 q-rows/block, 4 warps (16 rows each), key tiles of 64.
// bf16 hi/lo split, 3-term mma for both QK^T and PV (err ~2^-16).
// ---------------------------------------------------------------------------
#define KSTR 72              // bf16 elements per smem row (64 + 8 pad)
#define TILE_B (64 * KSTR * 2)   // 9216 bytes per bf16 tile

#define QH_OFF   0
#define QL_OFF   (QH_OFF + TILE_B)
#define KH_OFF   (QL_OFF + TILE_B)
#define KL_OFF   (KH_OFF + TILE_B)
#define VH_OFF   (KL_OFF + TILE_B)
#define VL_OFF   (VH_OFF + TILE_B)
#define SMALL_OFF (VL_OFF + TILE_B)          // 64*8 floats
#define PKS_OFF  (SMALL_OFF + 64*8*4)        // 7*64 floats
#define US_OFF   (PKS_OFF + NREL*64*4)       // 64 floats
#define CORR_OFF (US_OFF + 64*4)             // 8 floats
#define AT_SMEM  (CORR_OFF + 32)

__global__ __launch_bounds__(128, 2) void attn_mma(
    const float* __restrict__ q, const float* __restrict__ k,
    const float* __restrict__ v, const float* __restrict__ pk,
    const float* __restrict__ cbias, const float* __restrict__ rbias,
    float* __restrict__ out)
{
    extern __shared__ char smraw[];
    __nv_bfloat16* Qh = (__nv_bfloat16*)(smraw + QH_OFF);
    __nv_bfloat16* Ql = (__nv_bfloat16*)(smraw + QL_OFF);
    __nv_bfloat16* Kh = (__nv_bfloat16*)(smraw + KH_OFF);
    __nv_bfloat16* Kl = (__nv_bfloat16*)(smraw + KL_OFF);
    float* smalls = (float*)(smraw + SMALL_OFF);
    float* pks    = (float*)(smraw + PKS_OFF);
    float* us     = (float*)(smraw + US_OFF);
    float* corr   = (float*)(smraw + CORR_OFF);

    const int tid  = threadIdx.x;
    const int warp = tid >> 5;
    const int lane = tid & 31;
    const int g    = lane >> 2;     // 0..7
    const int t    = lane & 3;      // 0..3
    const int wm   = warp * 16;     // warp's 16 query rows
    const int h    = blockIdx.y;
    const int b    = blockIdx.z;
    const int q0   = blockIdx.x * 64;

    const float* qb = q + (size_t)b * TT * (HH * DH) + h * DH;
    const float* kb = k + (size_t)b * TT * (HH * DH) + h * DH;
    const float* vb = v + (size_t)b * TT * (HH * DH) + h * DH;

    // ---- prologue phase 1: us, pks ----
    if (tid < 64) us[tid] = cbias[h * DH + tid];
    for (int i = tid; i < NREL * 64; i += 128) {
        int r = i >> 6, d = i & 63;
        pks[i] = pk[r * DD + h * DH + d];
    }
    __syncthreads();

    // ---- prologue phase 2: Q (q + u) -> bf16 hi/lo smem; corr ----
    #pragma unroll
    for (int it = 0; it < 8; it++) {
        int l = tid + it * 128;            // 0..1023 float4 slots
        int row = l >> 4;                  // 0..63
        int d4 = (l & 15) << 2;
        float4 vq = *(const float4*)(qb + (size_t)(q0 + row) * (HH * DH) + d4);
        vq.x += us[d4 + 0]; vq.y += us[d4 + 1];
        vq.z += us[d4 + 2]; vq.w += us[d4 + 3];
        uint32_t h01, l01, h23, l23;
        split2_bf16(vq.x, vq.y, h01, l01);
        split2_bf16(vq.z, vq.w, h23, l23);
        *(uint32_t*)&Qh[row * KSTR + d4]     = h01;
        *(uint32_t*)&Qh[row * KSTR + d4 + 2] = h23;
        *(uint32_t*)&Ql[row * KSTR + d4]     = l01;
        *(uint32_t*)&Ql[row * KSTR + d4 + 2] = l23;
    }
    if (tid < NREL) {
        float s = 0.f;
        for (int d = 0; d < 64; d++)
            s += (rbias[h * DH + d] - us[d]) * pks[tid * 64 + d];
        corr[tid] = s;
    }
    __syncthreads();

    // ---- prologue phase 3: smalls[row][r] = (q_raw + rbias) . pk[r] ----
    if (tid < 64) {
        float accr[NREL];
        #pragma unroll
        for (int r = 0; r < NREL; r++) accr[r] = corr[r];
        for (int d = 0; d < 64; d++) {
            float qv = __bfloat162float(Qh[tid * KSTR + d]) +
                       __bfloat162float(Ql[tid * KSTR + d]);
            #pragma unroll
            for (int r = 0; r < NREL; r++) accr[r] += qv * pks[r * 64 + d];
        }
        #pragma unroll
        for (int r = 0; r < NREL; r++) smalls[tid * 8 + r] = accr[r];
    }

    // ---- load persistent Q fragments ----
    uint32_t qfh[4][4], qfl[4][4];
    #pragma unroll
    for (int ks = 0; ks < 4; ks++) {
        int d0 = 16 * ks + 2 * t;
        qfh[ks][0] = *(uint32_t*)&Qh[(wm + g) * KSTR + d0];
        qfh[ks][1] = *(uint32_t*)&Qh[(wm + g + 8) * KSTR + d0];
        qfh[ks][2] = *(uint32_t*)&Qh[(wm + g) * KSTR + d0 + 8];
        qfh[ks][3] = *(uint32_t*)&Qh[(wm + g + 8) * KSTR + d0 + 8];
        qfl[ks][0] = *(uint32_t*)&Ql[(wm + g) * KSTR + d0];
        qfl[ks][1] = *(uint32_t*)&Ql[(wm + g + 8) * KSTR + d0];
        qfl[ks][2] = *(uint32_t*)&Ql[(wm + g) * KSTR + d0 + 8];
        qfl[ks][3] = *(uint32_t*)&Ql[(wm + g + 8) * KSTR + d0 + 8];
    }

    const uint32_t vh_base = (uint32_t)__cvta_generic_to_shared(smraw + VH_OFF);
    const uint32_t vl_base = (uint32_t)__cvta_generic_to_shared(smraw + VL_OFF);
    const int lm = lane & 15;
    const uint32_t vh_lane = vh_base + (uint32_t)lm * (KSTR * 2);
    const uint32_t vl_lane = vl_base + (uint32_t)lm * (KSTR * 2);

    __nv_bfloat16* Vh = (__nv_bfloat16*)(smraw + VH_OFF);
    __nv_bfloat16* Vl = (__nv_bfloat16*)(smraw + VL_OFF);

    float m0 = -1e30f, m1 = -1e30f, l0 = 0.f, l1 = 0.f;
    float O[8][4];
    #pragma unroll
    for (int jd = 0; jd < 8; jd++)
        #pragma unroll
        for (int r = 0; r < 4; r++) O[jd][r] = 0.f;

    const float scale = 0.125f;
    const int tq0 = q0 + wm + g;
    const int rl0 = wm + g;

    for (int kt = 0; kt < TT; kt += 64) {
        __syncthreads();
        // ---- load + convert K and V tiles ----
        #pragma unroll
        for (int it = 0; it < 8; it++) {
            int l = tid + it * 128;
            int key = l >> 4;
            int d4 = (l & 15) << 2;
            float4 kv4 = *(const float4*)(kb + (size_t)(kt + key) * (HH * DH) + d4);
            uint32_t h01, l01, h23, l23;
            split2_bf16(kv4.x, kv4.y, h01, l01);
            split2_bf16(kv4.z, kv4.w, h23, l23);
            *(uint32_t*)&Kh[key * KSTR + d4]     = h01;
            *(uint32_t*)&Kh[key * KSTR + d4 + 2] = h23;
            *(uint32_t*)&Kl[key * KSTR + d4]     = l01;
            *(uint32_t*)&Kl[key * KSTR + d4 + 2] = l23;
            float4 vv4 = *(const float4*)(vb + (size_t)(kt + key) * (HH * DH) + d4);
            split2_bf16(vv4.x, vv4.y, h01, l01);
            split2_bf16(vv4.z, vv4.w, h23, l23);
            *(uint32_t*)&Vh[key * KSTR + d4]     = h01;
            *(uint32_t*)&Vh[key * KSTR + d4 + 2] = h23;
            *(uint32_t*)&Vl[key * KSTR + d4]     = l01;
            *(uint32_t*)&Vl[key * KSTR + d4 + 2] = l23;
        }
        __syncthreads();

        // ---- S = (q+u) K^T via 3-term bf16 mma ----
        float S[8][4];
        #pragma unroll
        for (int j = 0; j < 8; j++)
            #pragma unroll
            for (int r = 0; r < 4; r++) S[j][r] = 0.f;

        #pragma unroll
        for (int ks = 0; ks < 4; ks++) {
            const int d0 = 16 * ks + 2 * t;
            #pragma unroll
            for (int j = 0; j < 8; j++) {
                const int key = 8 * j + g;
                uint32_t bh0 = *(uint32_t*)&Kh[key * KSTR + d0];
                uint32_t bh1 = *(uint32_t*)&Kh[key * KSTR + d0 + 8];
                uint32_t bl0 = *(uint32_t*)&Kl[key * KSTR + d0];
                uint32_t bl1 = *(uint32_t*)&Kl[key * KSTR + d0 + 8];
                mma_bf16(S[j], qfh[ks], bh0, bh1);
                mma_bf16(S[j], qfh[ks], bl0, bl1);
                mma_bf16(S[j], qfl[ks], bh0, bh1);
            }
        }

        // ---- relative bias + scale + row max ----
        float mx0 = -1e30f, mx1 = -1e30f;
        #pragma unroll
        for (int j = 0; j < 8; j++) {
            #pragma unroll
            for (int c = 0; c < 2; c++) {
                int tk = kt + 8 * j + 2 * t + c;
                int d0 = min(3, max(-3, tq0 - tk)) + 3;
                int d1 = min(3, max(-3, tq0 + 8 - tk)) + 3;
                S[j][c]     = (S[j][c]     + smalls[rl0 * 8 + d0]) * scale;
                S[j][2 + c] = (S[j][2 + c] + smalls[(rl0 + 8) * 8 + d1]) * scale;
                mx0 = fmaxf(mx0, S[j][c]);
                mx1 = fmaxf(mx1, S[j][2 + c]);
            }
        }
        mx0 = fmaxf(mx0, __shfl_xor_sync(0xffffffffu, mx0, 1));
        mx0 = fmaxf(mx0, __shfl_xor_sync(0xffffffffu, mx0, 2));
        mx1 = fmaxf(mx1, __shfl_xor_sync(0xffffffffu, mx1, 1));
        mx1 = fmaxf(mx1, __shfl_xor_sync(0xffffffffu, mx1, 2));

        float mn0 = fmaxf(m0, mx0), mn1 = fmaxf(m1, mx1);
        float cr0 = __expf(m0 - mn0), cr1 = __expf(m1 - mn1);
        m0 = mn0; m1 = mn1;

        // ---- exp, row sums, pack P to bf16 hi/lo A-frags ----
        uint32_t phA[8], plA[8], phB[8], plB[8];
        float s0 = 0.f, s1 = 0.f;
        #pragma unroll
        for (int j = 0; j < 8; j++) {
            float p0 = __expf(S[j][0] - mn0);
            float p1 = __expf(S[j][1] - mn0);
            float p2 = __expf(S[j][2] - mn1);
            float p3 = __expf(S[j][3] - mn1);
            s0 += p0 + p1; s1 += p2 + p3;
            split2_bf16(p0, p1, phA[j], plA[j]);
            split2_bf16(p2, p3, phB[j], plB[j]);
        }
        s0 += __shfl_xor_sync(0xffffffffu, s0, 1);
        s0 += __shfl_xor_sync(0xffffffffu, s0, 2);
        s1 += __shfl_xor_sync(0xffffffffu, s1, 1);
        s1 += __shfl_xor_sync(0xffffffffu, s1, 2);
        l0 = l0 * cr0 + s0;
        l1 = l1 * cr1 + s1;

        #pragma unroll
        for (int jd = 0; jd < 8; jd++) {
            O[jd][0] *= cr0; O[jd][1] *= cr0;
            O[jd][2] *= cr1; O[jd][3] *= cr1;
        }

        // ---- O += P V via 3-term bf16 mma; V B-frags via ldmatrix.trans ----
        #pragma unroll
        for (int kv = 0; kv < 4; kv++) {
            uint32_t ah[4] = { phA[2*kv], phB[2*kv], phA[2*kv+1], phB[2*kv+1] };
            uint32_t al[4] = { plA[2*kv], plB[2*kv], plA[2*kv+1], plB[2*kv+1] };
            const uint32_t rh = vh_lane + (uint32_t)kv * 16 * (KSTR * 2);
            const uint32_t rl = vl_lane + (uint32_t)kv * 16 * (KSTR * 2);
            #pragma unroll
            for (int jd = 0; jd < 8; jd++) {
                uint32_t bh0, bh1, bl0, bl1;
                ldsm_x2_t(bh0, bh1, rh + jd * 16);
                ldsm_x2_t(bl0, bl1, rl + jd * 16);
                mma_bf16(O[jd], ah, bh0, bh1);
                mma_bf16(O[jd], ah, bl0, bl1);
                mma_bf16(O[jd], al, bh0, bh1);
            }
        }
    }

    // ---- epilogue ----
    float inv0 = 1.f / l0, inv1 = 1.f / l1;
    #pragma unroll
    for (int jd = 0; jd < 8; jd++) {
        int col = h * DH + 8 * jd + 2 * t;
        float2 o0 = make_float2(O[jd][0] * inv0, O[jd][1] * inv0);
        float2 o1 = make_float2(O[jd][2] * inv1, O[jd][3] * inv1);
        *(float2*)(out + ((size_t)b * TT + tq0) * (HH * DH) + col)     = o0;
        *(float2*)(out + ((size_t)b * TT + tq0 + 8) * (HH * DH) + col) = o1;
    }
}

// ---------------------------------------------------------------------------
extern "C" void kernel_launch(void* const* d_in, const int* in_sizes, int n_in,
                              void* d_out, int out_size)
{
    const float* query   = (const float*)d_in[0];
    const float* key_    = (const float*)d_in[1];
    const float* value   = (const float*)d_in[2];
    const float* Wq      = (const float*)d_in[3];
    const float* bq      = (const float*)d_in[4];
    const float* Wk      = (const float*)d_in[5];
    const float* bk      = (const float*)d_in[6];
    const float* Wv      = (const float*)d_in[7];
    const float* bv      = (const float*)d_in[8];
    const float* Wo      = (const float*)d_in[9];
    const float* bo      = (const float*)d_in[10];
    const float* cbias   = (const float*)d_in[11];
    const float* rbias   = (const float*)d_in[12];
    const float* pos_emb = (const float*)d_in[13];

    float *q, *k, *v, *attn, *pk;
    cudaGetSymbolAddress((void**)&q, g_q);
    cudaGetSymbolAddress((void**)&k, g_k);
    cudaGetSymbolAddress((void**)&v, g_v);
    cudaGetSymbolAddress((void**)&attn, g_attn);
    cudaGetSymbolAddress((void**)&pk, g_pk);

    const int M = BB * TT;     // 4096
    const int N = HH * DH;     // 1024
    const int K = DD;          // 1024

    dim3 gg(N / 128, M / 64);  // (8, 64)
    gemm_tf32<<<gg, 256>>>(query, Wq, bq, q, M, N, K);
    gemm_tf32<<<gg, 256>>>(key_,  Wk, bk, k, M, N, K);
    gemm_tf32<<<gg, 256>>>(value, Wv, bv, v, M, N, K);

    pk_init<<<(NREL * DD + 255) / 256, 256>>>(bk, pk);
    pk_gemm_split<<<dim3(DD / 256, DD / 128), 256>>>(pos_emb, Wk, pk);

    cudaFuncSetAttribute(attn_mma,
                         cudaFuncAttributeMaxDynamicSharedMemorySize, AT_SMEM);
    attn_mma<<<dim3(TT / 64, HH, BB), 128, AT_SMEM>>>(q, k, v, pk,
                                                      cbias, rbias, attn);

    // output projection -> d_out
    gemm_tf32<<<gg, 256>>>(attn, Wo, bo, (float*)d_out, M, N, K);
}

// round 7
// speedup vs baseline: 3.8887x; 1.1972x over previous
#include <cuda_runtime.h>
#include <cuda_bf16.h>
#include <math.h>
#include <stdint.h>

#define BB 2
#define TT 2048
#define DD 1024
#define HH 16
#define DH 64
#define NREL 7

// Scratch (static device globals — no allocation)
__device__ float g_q[BB*TT*HH*DH];
__device__ float g_k[BB*TT*HH*DH];
__device__ float g_v[BB*TT*HH*DH];
__device__ float g_attn[BB*TT*HH*DH];
__device__ float g_pk[NREL*HH*DH];

// ---------------------------------------------------------------------------
// helpers
// ---------------------------------------------------------------------------
__device__ __forceinline__ void cp16(void* smem, const void* gmem) {
    uint32_t s = (uint32_t)__cvta_generic_to_shared(smem);
    asm volatile("cp.async.ca.shared.global [%0], [%1], 16;\n" :: "r"(s), "l"(gmem));
}
__device__ __forceinline__ void cp_commit() {
    asm volatile("cp.async.commit_group;\n");
}
__device__ __forceinline__ void cp_wait1() {
    asm volatile("cp.async.wait_group 1;\n");
}

__device__ __forceinline__ void mma_bf16(float* c, const uint32_t* a,
                                         uint32_t b0, uint32_t b1) {
    asm volatile(
        "mma.sync.aligned.m16n8k16.row.col.f32.bf16.bf16.f32 "
        "{%0,%1,%2,%3}, {%4,%5,%6,%7}, {%8,%9}, {%0,%1,%2,%3};"
        : "+f"(c[0]), "+f"(c[1]), "+f"(c[2]), "+f"(c[3])
        : "r"(a[0]), "r"(a[1]), "r"(a[2]), "r"(a[3]), "r"(b0), "r"(b1));
}

__device__ __forceinline__ void ldsm_x2_t(uint32_t& r0, uint32_t& r1, uint32_t addr) {
    asm volatile("ldmatrix.sync.aligned.m8n8.x2.trans.shared.b16 {%0,%1}, [%2];"
                 : "=r"(r0), "=r"(r1) : "r"(addr));
}

// pack two floats into bf16x2 hi word + bf16x2 residual word
__device__ __forceinline__ void split2_bf16(float x0, float x1,
                                            uint32_t& hi, uint32_t& lo) {
    __nv_bfloat16 h0 = __float2bfloat16_rn(x0);
    __nv_bfloat16 h1 = __float2bfloat16_rn(x1);
    float r0 = x0 - __bfloat162float(h0);
    float r1 = x1 - __bfloat162float(h1);
    __nv_bfloat162 H = __halves2bfloat162(h0, h1);
    __nv_bfloat162 L = __halves2bfloat162(__float2bfloat16_rn(r0),
                                          __float2bfloat16_rn(r1));
    hi = *(uint32_t*)&H;
    lo = *(uint32_t*)&L;
}

// ---------------------------------------------------------------------------
// 3xBF16 tensor-core GEMM: C[M,N] = A[M,K] @ W[K,N] + bias[N]
// BM=64, BN=128, BK=16, 256 threads (8 warps 2x4), warp tile 32x32.
// Raw fp32 in smem (cp.async 3-stage); bf16 hi/lo split in registers;
// one m16n8k16 mma per k16 (half the instruction count of the tf32 version).
// ---------------------------------------------------------------------------
#define ASTRIDE 20
#define BSTRIDE 132   // ≡ 4 mod 32 -> both k-row phases conflict-free

__global__ __launch_bounds__(256, 2) void gemm_bf16x3(
    const float* __restrict__ A, const float* __restrict__ W,
    const float* __restrict__ bias, float* __restrict__ C,
    int M, int N, int K)
{
    __shared__ float As[3][64][ASTRIDE];    // m-major raw fp32
    __shared__ float Bs[3][16][BSTRIDE];    // k-major raw fp32

    const int tid  = threadIdx.x;
    const int warp = tid >> 5;
    const int lane = tid & 31;
    const int g    = lane >> 2;      // 0..7
    const int t    = lane & 3;       // 0..3
    const int wm   = (warp & 1) * 32;
    const int wn   = (warp >> 1) * 32;
    const int bm   = blockIdx.y * 64;
    const int bn   = blockIdx.x * 128;

    const int a_row = tid >> 2;
    const int a_c4  = (tid & 3) << 2;
    const float* a_src = A + (size_t)(bm + a_row) * K + a_c4;

    const int b_row0 = tid >> 5;
    const int b_n4   = (tid & 31) << 2;
    const float* b_src = W + (size_t)b_row0 * N + bn + b_n4;

    const int NIT = K >> 4;

    #pragma unroll
    for (int s = 0; s < 2; s++) {
        cp16(&As[s][a_row][a_c4], a_src + s * 16);
        cp16(&Bs[s][b_row0][b_n4],     b_src + (size_t)(s * 16) * N);
        cp16(&Bs[s][b_row0 + 8][b_n4], b_src + (size_t)(s * 16 + 8) * N);
        cp_commit();
    }

    float acc[2][4][4];
    #pragma unroll
    for (int i = 0; i < 2; i++)
        #pragma unroll
        for (int j = 0; j < 4; j++)
            #pragma unroll
            for (int r = 0; r < 4; r++) acc[i][j][r] = 0.f;

    for (int it = 0; it < NIT; it++) {
        const int s = it % 3;
        cp_wait1();
        __syncthreads();

        if (it + 2 < NIT) {
            const int sn = (it + 2) % 3;
            const int k0 = (it + 2) * 16;
            cp16(&As[sn][a_row][a_c4], a_src + k0);
            cp16(&Bs[sn][b_row0][b_n4],     b_src + (size_t)k0 * N);
            cp16(&Bs[sn][b_row0 + 8][b_n4], b_src + (size_t)(k0 + 8) * N);
        }
        cp_commit();

        // A fragments (2 m-tiles), k16, hi/lo in regs
        uint32_t ah[2][4], al[2][4];
        #pragma unroll
        for (int i = 0; i < 2; i++) {
            const int r0 = wm + i * 16 + g;
            float2 x0 = *(float2*)&As[s][r0][2 * t];
            float2 x1 = *(float2*)&As[s][r0 + 8][2 * t];
            float2 x2 = *(float2*)&As[s][r0][2 * t + 8];
            float2 x3 = *(float2*)&As[s][r0 + 8][2 * t + 8];
            split2_bf16(x0.x, x0.y, ah[i][0], al[i][0]);
            split2_bf16(x1.x, x1.y, ah[i][1], al[i][1]);
            split2_bf16(x2.x, x2.y, ah[i][2], al[i][2]);
            split2_bf16(x3.x, x3.y, ah[i][3], al[i][3]);
        }
        // B fragments (4 n-tiles): issue all 4 row loads before converting
        #pragma unroll
        for (int j = 0; j < 4; j++) {
            const int nc = wn + j * 8 + g;
            float y0 = Bs[s][2 * t][nc];
            float y1 = Bs[s][2 * t + 1][nc];
            float y2 = Bs[s][2 * t + 8][nc];
            float y3 = Bs[s][2 * t + 9][nc];
            uint32_t bh0, bl0, bh1, bl1;
            split2_bf16(y0, y1, bh0, bl0);
            split2_bf16(y2, y3, bh1, bl1);
            #pragma unroll
            for (int i = 0; i < 2; i++) {
                mma_bf16(acc[i][j], ah[i], bh0, bh1);
                mma_bf16(acc[i][j], ah[i], bl0, bl1);
                mma_bf16(acc[i][j], al[i], bh0, bh1);
            }
        }
        __syncthreads();
    }

    // epilogue: bias + store (same C layout as before)
    #pragma unroll
    for (int j = 0; j < 4; j++) {
        const int col = bn + wn + j * 8 + 2 * t;
        const float bv0 = bias[col];
        const float bv1 = bias[col + 1];
        #pragma unroll
        for (int i = 0; i < 2; i++) {
            const int row0 = bm + wm + i * 16 + g;
            float2 v0 = make_float2(acc[i][j][0] + bv0, acc[i][j][1] + bv1);
            float2 v1 = make_float2(acc[i][j][2] + bv0, acc[i][j][3] + bv1);
            *(float2*)(C + (size_t)row0 * N + col)       = v0;
            *(float2*)(C + (size_t)(row0 + 8) * N + col) = v1;
        }
    }
}

// ---------------------------------------------------------------------------
// pk path (unchanged)
// ---------------------------------------------------------------------------
__global__ void pk_init(const float* __restrict__ bk, float* __restrict__ pk)
{
    int i = blockIdx.x * 256 + threadIdx.x;
    if (i < NREL * DD) pk[i] = bk[i & (DD - 1)];
}

__global__ __launch_bounds__(256) void pk_gemm_split(
    const float* __restrict__ pos_emb, const float* __restrict__ Wk,
    float* __restrict__ pk)
{
    __shared__ float pe_s[NREL][128];
    const int n  = blockIdx.x * 256 + threadIdx.x;
    const int k0 = blockIdx.y * 128;

    for (int i = threadIdx.x; i < NREL * 128; i += 256) {
        int r = i >> 7, kk = i & 127;
        pe_s[r][kk] = pos_emb[r * DD + k0 + kk];
    }
    __syncthreads();

    float acc[NREL];
    #pragma unroll
    for (int r = 0; r < NREL; r++) acc[r] = 0.f;

    #pragma unroll 4
    for (int kk = 0; kk < 128; kk++) {
        float w = Wk[(size_t)(k0 + kk) * DD + n];
        #pragma unroll
        for (int r = 0; r < NREL; r++) acc[r] += pe_s[r][kk] * w;
    }
    #pragma unroll
    for (int r = 0; r < NREL; r++)
        atomicAdd(&pk[r * DD + n], acc[r]);
}

// ---------------------------------------------------------------------------
// Tensor-core flash attention with TransformerXL relative bias (proven R5).
// ---------------------------------------------------------------------------
#define KSTR 72
#define TILE_B (64 * KSTR * 2)

#define QH_OFF   0
#define QL_OFF   (QH_OFF + TILE_B)
#define KH_OFF   (QL_OFF + TILE_B)
#define KL_OFF   (KH_OFF + TILE_B)
#define VH_OFF   (KL_OFF + TILE_B)
#define VL_OFF   (VH_OFF + TILE_B)
#define SMALL_OFF (VL_OFF + TILE_B)
#define PKS_OFF  (SMALL_OFF + 64*8*4)
#define US_OFF   (PKS_OFF + NREL*64*4)
#define CORR_OFF (US_OFF + 64*4)
#define AT_SMEM  (CORR_OFF + 32)

__global__ __launch_bounds__(128, 2) void attn_mma(
    const float* __restrict__ q, const float* __restrict__ k,
    const float* __restrict__ v, const float* __restrict__ pk,
    const float* __restrict__ cbias, const float* __restrict__ rbias,
    float* __restrict__ out)
{
    extern __shared__ char smraw[];
    __nv_bfloat16* Qh = (__nv_bfloat16*)(smraw + QH_OFF);
    __nv_bfloat16* Ql = (__nv_bfloat16*)(smraw + QL_OFF);
    __nv_bfloat16* Kh = (__nv_bfloat16*)(smraw + KH_OFF);
    __nv_bfloat16* Kl = (__nv_bfloat16*)(smraw + KL_OFF);
    float* smalls = (float*)(smraw + SMALL_OFF);
    float* pks    = (float*)(smraw + PKS_OFF);
    float* us     = (float*)(smraw + US_OFF);
    float* corr   = (float*)(smraw + CORR_OFF);

    const int tid  = threadIdx.x;
    const int warp = tid >> 5;
    const int lane = tid & 31;
    const int g    = lane >> 2;
    const int t    = lane & 3;
    const int wm   = warp * 16;
    const int h    = blockIdx.y;
    const int b    = blockIdx.z;
    const int q0   = blockIdx.x * 64;

    const float* qb = q + (size_t)b * TT * (HH * DH) + h * DH;
    const float* kb = k + (size_t)b * TT * (HH * DH) + h * DH;
    const float* vb = v + (size_t)b * TT * (HH * DH) + h * DH;

    if (tid < 64) us[tid] = cbias[h * DH + tid];
    for (int i = tid; i < NREL * 64; i += 128) {
        int r = i >> 6, d = i & 63;
        pks[i] = pk[r * DD + h * DH + d];
    }
    __syncthreads();

    #pragma unroll
    for (int it = 0; it < 8; it++) {
        int l = tid + it * 128;
        int row = l >> 4;
        int d4 = (l & 15) << 2;
        float4 vq = *(const float4*)(qb + (size_t)(q0 + row) * (HH * DH) + d4);
        vq.x += us[d4 + 0]; vq.y += us[d4 + 1];
        vq.z += us[d4 + 2]; vq.w += us[d4 + 3];
        uint32_t h01, l01, h23, l23;
        split2_bf16(vq.x, vq.y, h01, l01);
        split2_bf16(vq.z, vq.w, h23, l23);
        *(uint32_t*)&Qh[row * KSTR + d4]     = h01;
        *(uint32_t*)&Qh[row * KSTR + d4 + 2] = h23;
        *(uint32_t*)&Ql[row * KSTR + d4]     = l01;
        *(uint32_t*)&Ql[row * KSTR + d4 + 2] = l23;
    }
    if (tid < NREL) {
        float s = 0.f;
        for (int d = 0; d < 64; d++)
            s += (rbias[h * DH + d] - us[d]) * pks[tid * 64 + d];
        corr[tid] = s;
    }
    __syncthreads();

    if (tid < 64) {
        float accr[NREL];
        #pragma unroll
        for (int r = 0; r < NREL; r++) accr[r] = corr[r];
        for (int d = 0; d < 64; d++) {
            float qv = __bfloat162float(Qh[tid * KSTR + d]) +
                       __bfloat162float(Ql[tid * KSTR + d]);
            #pragma unroll
            for (int r = 0; r < NREL; r++) accr[r] += qv * pks[r * 64 + d];
        }
        #pragma unroll
        for (int r = 0; r < NREL; r++) smalls[tid * 8 + r] = accr[r];
    }

    uint32_t qfh[4][4], qfl[4][4];
    #pragma unroll
    for (int ks = 0; ks < 4; ks++) {
        int d0 = 16 * ks + 2 * t;
        qfh[ks][0] = *(uint32_t*)&Qh[(wm + g) * KSTR + d0];
        qfh[ks][1] = *(uint32_t*)&Qh[(wm + g + 8) * KSTR + d0];
        qfh[ks][2] = *(uint32_t*)&Qh[(wm + g) * KSTR + d0 + 8];
        qfh[ks][3] = *(uint32_t*)&Qh[(wm + g + 8) * KSTR + d0 + 8];
        qfl[ks][0] = *(uint32_t*)&Ql[(wm + g) * KSTR + d0];
        qfl[ks][1] = *(uint32_t*)&Ql[(wm + g + 8) * KSTR + d0];
        qfl[ks][2] = *(uint32_t*)&Ql[(wm + g) * KSTR + d0 + 8];
        qfl[ks][3] = *(uint32_t*)&Ql[(wm + g + 8) * KSTR + d0 + 8];
    }

    const uint32_t vh_base = (uint32_t)__cvta_generic_to_shared(smraw + VH_OFF);
    const uint32_t vl_base = (uint32_t)__cvta_generic_to_shared(smraw + VL_OFF);
    const int lm = lane & 15;
    const uint32_t vh_lane = vh_base + (uint32_t)lm * (KSTR * 2);
    const uint32_t vl_lane = vl_base + (uint32_t)lm * (KSTR * 2);

    __nv_bfloat16* Vh = (__nv_bfloat16*)(smraw + VH_OFF);
    __nv_bfloat16* Vl = (__nv_bfloat16*)(smraw + VL_OFF);

    float m0 = -1e30f, m1 = -1e30f, l0 = 0.f, l1 = 0.f;
    float O[8][4];
    #pragma unroll
    for (int jd = 0; jd < 8; jd++)
        #pragma unroll
        for (int r = 0; r < 4; r++) O[jd][r] = 0.f;

    const float scale = 0.125f;
    const int tq0 = q0 + wm + g;
    const int rl0 = wm + g;

    for (int kt = 0; kt < TT; kt += 64) {
        __syncthreads();
        #pragma unroll
        for (int it = 0; it < 8; it++) {
            int l = tid + it * 128;
            int key = l >> 4;
            int d4 = (l & 15) << 2;
            float4 kv4 = *(const float4*)(kb + (size_t)(kt + key) * (HH * DH) + d4);
            uint32_t h01, l01, h23, l23;
            split2_bf16(kv4.x, kv4.y, h01, l01);
            split2_bf16(kv4.z, kv4.w, h23, l23);
            *(uint32_t*)&Kh[key * KSTR + d4]     = h01;
            *(uint32_t*)&Kh[key * KSTR + d4 + 2] = h23;
            *(uint32_t*)&Kl[key * KSTR + d4]     = l01;
            *(uint32_t*)&Kl[key * KSTR + d4 + 2] = l23;
            float4 vv4 = *(const float4*)(vb + (size_t)(kt + key) * (HH * DH) + d4);
            split2_bf16(vv4.x, vv4.y, h01, l01);
            split2_bf16(vv4.z, vv4.w, h23, l23);
            *(uint32_t*)&Vh[key * KSTR + d4]     = h01;
            *(uint32_t*)&Vh[key * KSTR + d4 + 2] = h23;
            *(uint32_t*)&Vl[key * KSTR + d4]     = l01;
            *(uint32_t*)&Vl[key * KSTR + d4 + 2] = l23;
        }
        __syncthreads();

        float S[8][4];
        #pragma unroll
        for (int j = 0; j < 8; j++)
            #pragma unroll
            for (int r = 0; r < 4; r++) S[j][r] = 0.f;

        #pragma unroll
        for (int ks = 0; ks < 4; ks++) {
            const int d0 = 16 * ks + 2 * t;
            #pragma unroll
            for (int j = 0; j < 8; j++) {
                const int key = 8 * j + g;
                uint32_t bh0 = *(uint32_t*)&Kh[key * KSTR + d0];
                uint32_t bh1 = *(uint32_t*)&Kh[key * KSTR + d0 + 8];
                uint32_t bl0 = *(uint32_t*)&Kl[key * KSTR + d0];
                uint32_t bl1 = *(uint32_t*)&Kl[key * KSTR + d0 + 8];
                mma_bf16(S[j], qfh[ks], bh0, bh1);
                mma_bf16(S[j], qfh[ks], bl0, bl1);
                mma_bf16(S[j], qfl[ks], bh0, bh1);
            }
        }

        float mx0 = -1e30f, mx1 = -1e30f;
        #pragma unroll
        for (int j = 0; j < 8; j++) {
            #pragma unroll
            for (int c = 0; c < 2; c++) {
                int tk = kt + 8 * j + 2 * t + c;
                int d0 = min(3, max(-3, tq0 - tk)) + 3;
                int d1 = min(3, max(-3, tq0 + 8 - tk)) + 3;
                S[j][c]     = (S[j][c]     + smalls[rl0 * 8 + d0]) * scale;
                S[j][2 + c] = (S[j][2 + c] + smalls[(rl0 + 8) * 8 + d1]) * scale;
                mx0 = fmaxf(mx0, S[j][c]);
                mx1 = fmaxf(mx1, S[j][2 + c]);
            }
        }
        mx0 = fmaxf(mx0, __shfl_xor_sync(0xffffffffu, mx0, 1));
        mx0 = fmaxf(mx0, __shfl_xor_sync(0xffffffffu, mx0, 2));
        mx1 = fmaxf(mx1, __shfl_xor_sync(0xffffffffu, mx1, 1));
        mx1 = fmaxf(mx1, __shfl_xor_sync(0xffffffffu, mx1, 2));

        float mn0 = fmaxf(m0, mx0), mn1 = fmaxf(m1, mx1);
        float cr0 = __expf(m0 - mn0), cr1 = __expf(m1 - mn1);
        m0 = mn0; m1 = mn1;

        uint32_t phA[8], plA[8], phB[8], plB[8];
        float s0 = 0.f, s1 = 0.f;
        #pragma unroll
        for (int j = 0; j < 8; j++) {
            float p0 = __expf(S[j][0] - mn0);
            float p1 = __expf(S[j][1] - mn0);
            float p2 = __expf(S[j][2] - mn1);
            float p3 = __expf(S[j][3] - mn1);
            s0 += p0 + p1; s1 += p2 + p3;
            split2_bf16(p0, p1, phA[j], plA[j]);
            split2_bf16(p2, p3, phB[j], plB[j]);
        }
        s0 += __shfl_xor_sync(0xffffffffu, s0, 1);
        s0 += __shfl_xor_sync(0xffffffffu, s0, 2);
        s1 += __shfl_xor_sync(0xffffffffu, s1, 1);
        s1 += __shfl_xor_sync(0xffffffffu, s1, 2);
        l0 = l0 * cr0 + s0;
        l1 = l1 * cr1 + s1;

        #pragma unroll
        for (int jd = 0; jd < 8; jd++) {
            O[jd][0] *= cr0; O[jd][1] *= cr0;
            O[jd][2] *= cr1; O[jd][3] *= cr1;
        }

        #pragma unroll
        for (int kv = 0; kv < 4; kv++) {
            uint32_t ah[4] = { phA[2*kv], phB[2*kv], phA[2*kv+1], phB[2*kv+1] };
            uint32_t al[4] = { plA[2*kv], plB[2*kv], plA[2*kv+1], plB[2*kv+1] };
            const uint32_t rh = vh_lane + (uint32_t)kv * 16 * (KSTR * 2);
            const uint32_t rl = vl_lane + (uint32_t)kv * 16 * (KSTR * 2);
            #pragma unroll
            for (int jd = 0; jd < 8; jd++) {
                uint32_t bh0, bh1, bl0, bl1;
                ldsm_x2_t(bh0, bh1, rh + jd * 16);
                ldsm_x2_t(bl0, bl1, rl + jd * 16);
                mma_bf16(O[jd], ah, bh0, bh1);
                mma_bf16(O[jd], ah, bl0, bl1);
                mma_bf16(O[jd], al, bh0, bh1);
            }
        }
    }

    float inv0 = 1.f / l0, inv1 = 1.f / l1;
    #pragma unroll
    for (int jd = 0; jd < 8; jd++) {
        int col = h * DH + 8 * jd + 2 * t;
        float2 o0 = make_float2(O[jd][0] * inv0, O[jd][1] * inv0);
        float2 o1 = make_float2(O[jd][2] * inv1, O[jd][3] * inv1);
        *(float2*)(out + ((size_t)b * TT + tq0) * (HH * DH) + col)     = o0;
        *(float2*)(out + ((size_t)b * TT + tq0 + 8) * (HH * DH) + col) = o1;
    }
}

// ---------------------------------------------------------------------------
extern "C" void kernel_launch(void* const* d_in, const int* in_sizes, int n_in,
                              void* d_out, int out_size)
{
    const float* query   = (const float*)d_in[0];
    const float* key_    = (const float*)d_in[1];
    const float* value   = (const float*)d_in[2];
    const float* Wq      = (const float*)d_in[3];
    const float* bq      = (const float*)d_in[4];
    const float* Wk      = (const float*)d_in[5];
    const float* bk      = (const float*)d_in[6];
    const float* Wv      = (const float*)d_in[7];
    const float* bv      = (const float*)d_in[8];
    const float* Wo      = (const float*)d_in[9];
    const float* bo      = (const float*)d_in[10];
    const float* cbias   = (const float*)d_in[11];
    const float* rbias   = (const float*)d_in[12];
    const float* pos_emb = (const float*)d_in[13];

    float *q, *k, *v, *attn, *pk;
    cudaGetSymbolAddress((void**)&q, g_q);
    cudaGetSymbolAddress((void**)&k, g_k);
    cudaGetSymbolAddress((void**)&v, g_v);
    cudaGetSymbolAddress((void**)&attn, g_attn);
    cudaGetSymbolAddress((void**)&pk, g_pk);

    const int M = BB * TT;     // 4096
    const int N = HH * DH;     // 1024
    const int K = DD;          // 1024

    dim3 gg(N / 128, M / 64);  // (8, 64)
    gemm_bf16x3<<<gg, 256>>>(query, Wq, bq, q, M, N, K);
    gemm_bf16x3<<<gg, 256>>>(key_,  Wk, bk, k, M, N, K);
    gemm_bf16x3<<<gg, 256>>>(value, Wv, bv, v, M, N, K);

    pk_init<<<(NREL * DD + 255) / 256, 256>>>(bk, pk);
    pk_gemm_split<<<dim3(DD / 256, DD / 128), 256>>>(pos_emb, Wk, pk);

    cudaFuncSetAttribute(attn_mma,
                         cudaFuncAttributeMaxDynamicSharedMemorySize, AT_SMEM);
    attn_mma<<<dim3(TT / 64, HH, BB), 128, AT_SMEM>>>(q, k, v, pk,
                                                      cbias, rbias, attn);

    // output projection -> d_out
    gemm_bf16x3<<<gg, 256>>>(attn, Wo, bo, (float*)d_out, M, N, K);
}

// round 10
// speedup vs baseline: 4.3635x; 1.1221x over previous
#include <cuda_runtime.h>
#include <cuda_bf16.h>
#include <math.h>
#include <stdint.h>

#define BB 2
#define TT 2048
#define DD 1024
#define HH 16
#define DH 64
#define NREL 7

// Scratch (static device globals — no allocation)
__device__ float g_q[BB*TT*HH*DH];
__device__ float g_k[BB*TT*HH*DH];
__device__ float g_v[BB*TT*HH*DH];
__device__ float g_attn[BB*TT*HH*DH];
__device__ float g_pk[NREL*HH*DH];

// packed bf16 hi/lo planes
__device__ __nv_bfloat16 g_wq_h[DD*HH*DH], g_wq_l[DD*HH*DH];
__device__ __nv_bfloat16 g_wk_h[DD*HH*DH], g_wk_l[DD*HH*DH];
__device__ __nv_bfloat16 g_wv_h[DD*HH*DH], g_wv_l[DD*HH*DH];
__device__ __nv_bfloat16 g_wo_h[DD*HH*DH], g_wo_l[DD*HH*DH];
__device__ __nv_bfloat16 g_x_h[BB*TT*DD],  g_x_l[BB*TT*DD];   // query
__device__ __nv_bfloat16 g_y_h[BB*TT*DD],  g_y_l[BB*TT*DD];   // key
__device__ __nv_bfloat16 g_z_h[BB*TT*DD],  g_z_l[BB*TT*DD];   // value
__device__ __nv_bfloat16 g_a_h[BB*TT*DD],  g_a_l[BB*TT*DD];   // attn out

// ---------------------------------------------------------------------------
// helpers
// ---------------------------------------------------------------------------
__device__ __forceinline__ void cp16(void* smem, const void* gmem) {
    uint32_t s = (uint32_t)__cvta_generic_to_shared(smem);
    asm volatile("cp.async.ca.shared.global [%0], [%1], 16;\n" :: "r"(s), "l"(gmem));
}
__device__ __forceinline__ void cp_commit() {
    asm volatile("cp.async.commit_group;\n");
}
__device__ __forceinline__ void cp_wait1() {
    asm volatile("cp.async.wait_group 1;\n");
}

__device__ __forceinline__ void mma_bf16(float* c, const uint32_t* a,
                                         uint32_t b0, uint32_t b1) {
    asm volatile(
        "mma.sync.aligned.m16n8k16.row.col.f32.bf16.bf16.f32 "
        "{%0,%1,%2,%3}, {%4,%5,%6,%7}, {%8,%9}, {%0,%1,%2,%3};"
        : "+f"(c[0]), "+f"(c[1]), "+f"(c[2]), "+f"(c[3])
        : "r"(a[0]), "r"(a[1]), "r"(a[2]), "r"(a[3]), "r"(b0), "r"(b1));
}

__device__ __forceinline__ void ldsm_x2_t(uint32_t& r0, uint32_t& r1, uint32_t addr) {
    asm volatile("ldmatrix.sync.aligned.m8n8.x2.trans.shared.b16 {%0,%1}, [%2];"
                 : "=r"(r0), "=r"(r1) : "r"(addr));
}
__device__ __forceinline__ void ldsm_x4(uint32_t* r, uint32_t addr) {
    asm volatile("ldmatrix.sync.aligned.m8n8.x4.shared.b16 {%0,%1,%2,%3}, [%4];"
                 : "=r"(r[0]), "=r"(r[1]), "=r"(r[2]), "=r"(r[3]) : "r"(addr));
}

// pack two floats into bf16x2 hi word + bf16x2 residual word
__device__ __forceinline__ void split2_bf16(float x0, float x1,
                                            uint32_t& hi, uint32_t& lo) {
    __nv_bfloat16 h0 = __float2bfloat16_rn(x0);
    __nv_bfloat16 h1 = __float2bfloat16_rn(x1);
    float r0 = x0 - __bfloat162float(h0);
    float r1 = x1 - __bfloat162float(h1);
    __nv_bfloat162 H = __halves2bfloat162(h0, h1);
    __nv_bfloat162 L = __halves2bfloat162(__float2bfloat16_rn(r0),
                                          __float2bfloat16_rn(r1));
    hi = *(uint32_t*)&H;
    lo = *(uint32_t*)&L;
}

// ---------------------------------------------------------------------------
// pack fp32 -> bf16 hi/lo planes
// ---------------------------------------------------------------------------
__global__ __launch_bounds__(256) void pack_bf16(
    const float* __restrict__ src, __nv_bfloat16* __restrict__ hi,
    __nv_bfloat16* __restrict__ lo, int n4)
{
    int i = blockIdx.x * 256 + threadIdx.x;
    if (i < n4) {
        float4 v = ((const float4*)src)[i];
        uint32_t h01, l01, h23, l23;
        split2_bf16(v.x, v.y, h01, l01);
        split2_bf16(v.z, v.w, h23, l23);
        ((uint2*)hi)[i] = make_uint2(h01, h23);
        ((uint2*)lo)[i] = make_uint2(l01, l23);
    }
}

// ---------------------------------------------------------------------------
// packed-bf16 3-term tensor GEMM: C[M,N] = A@W + bias, A/W pre-split hi/lo.
// BM=64, BN=128, BK=16, 256 threads (8 warps 2x4), warp tile 32x32.
// Fragments via ldmatrix; inner loop is ldmatrix + mma only.
// ---------------------------------------------------------------------------
#define APAD 24     // bf16 elems per A row (48B: rows distinct mod 128)
#define BPAD 136    // bf16 elems per B row (272B ≡ 16 mod 128)

__global__ __launch_bounds__(256, 2) void gemm_bf16p(
    const __nv_bfloat16* __restrict__ Ah_g, const __nv_bfloat16* __restrict__ Al_g,
    const __nv_bfloat16* __restrict__ Bh_g, const __nv_bfloat16* __restrict__ Bl_g,
    const float* __restrict__ bias, float* __restrict__ C,
    int M, int N, int K)
{
    __shared__ __align__(16) __nv_bfloat16 Ah[3][64][APAD];
    __shared__ __align__(16) __nv_bfloat16 Al[3][64][APAD];
    __shared__ __align__(16) __nv_bfloat16 Bh[3][16][BPAD];
    __shared__ __align__(16) __nv_bfloat16 Bl[3][16][BPAD];

    const int tid  = threadIdx.x;
    const int warp = tid >> 5;
    const int lane = tid & 31;
    const int t    = lane & 3;
    const int wm   = (warp & 1) * 32;
    const int wn   = (warp >> 1) * 32;
    const int bm   = blockIdx.y * 64;
    const int bn   = blockIdx.x * 128;

    // A fill: 64 rows x 16 elems = 128 16B-chunks per plane; tid<128 -> hi, else lo
    const int a_row = (tid & 127) >> 1;
    const int a_c8  = (tid & 1) * 8;
    const __nv_bfloat16* a_src =
        ((tid < 128) ? Ah_g : Al_g) + (size_t)(bm + a_row) * K + a_c8;

    // B fill: 16 rows x 128 elems = 256 chunks per plane; each thread 1 hi + 1 lo
    const int b_row = tid >> 4;
    const int b_c8  = (tid & 15) * 8;
    const __nv_bfloat16* bh_src = Bh_g + (size_t)b_row * N + bn + b_c8;
    const __nv_bfloat16* bl_src = Bl_g + (size_t)b_row * N + bn + b_c8;

    const int NIT = K >> 4;

    #pragma unroll
    for (int s = 0; s < 2; s++) {
        if (tid < 128) cp16(&Ah[s][a_row][a_c8], a_src + s * 16);
        else           cp16(&Al[s][a_row][a_c8], a_src + s * 16);
        cp16(&Bh[s][b_row][b_c8], bh_src + (size_t)(s * 16) * N);
        cp16(&Bl[s][b_row][b_c8], bl_src + (size_t)(s * 16) * N);
        cp_commit();
    }

    float acc[2][4][4];
    #pragma unroll
    for (int i = 0; i < 2; i++)
        #pragma unroll
        for (int j = 0; j < 4; j++)
            #pragma unroll
            for (int r = 0; r < 4; r++) acc[i][j][r] = 0.f;

    // ldmatrix lane addressing
    const int lm   = lane & 15;
    const int lq   = lane >> 4;
    const uint32_t a_frag_off = (uint32_t)(wm + lm) * (APAD * 2) + lq * 16;
    const uint32_t b_frag_off = (uint32_t)lm * (BPAD * 2) + (uint32_t)wn * 2;

    for (int it = 0; it < NIT; it++) {
        const int s = it % 3;
        cp_wait1();
        __syncthreads();

        if (it + 2 < NIT) {
            const int sn = (it + 2) % 3;
            const int k0 = (it + 2) * 16;
            if (tid < 128) cp16(&Ah[sn][a_row][a_c8], a_src + k0);
            else           cp16(&Al[sn][a_row][a_c8], a_src + k0);
            cp16(&Bh[sn][b_row][b_c8], bh_src + (size_t)k0 * N);
            cp16(&Bl[sn][b_row][b_c8], bl_src + (size_t)k0 * N);
        }
        cp_commit();

        const uint32_t ah_base = (uint32_t)__cvta_generic_to_shared(&Ah[s][0][0]);
        const uint32_t al_base = (uint32_t)__cvta_generic_to_shared(&Al[s][0][0]);
        const uint32_t bh_base = (uint32_t)__cvta_generic_to_shared(&Bh[s][0][0]);
        const uint32_t bl_base = (uint32_t)__cvta_generic_to_shared(&Bl[s][0][0]);

        uint32_t ah[2][4], al[2][4];
        ldsm_x4(ah[0], ah_base + a_frag_off);
        ldsm_x4(ah[1], ah_base + a_frag_off + 16 * (APAD * 2));
        ldsm_x4(al[0], al_base + a_frag_off);
        ldsm_x4(al[1], al_base + a_frag_off + 16 * (APAD * 2));

        #pragma unroll
        for (int j = 0; j < 4; j++) {
            uint32_t bh0, bh1, bl0, bl1;
            ldsm_x2_t(bh0, bh1, bh_base + b_frag_off + j * 16);
            ldsm_x2_t(bl0, bl1, bl_base + b_frag_off + j * 16);
            #pragma unroll
            for (int i = 0; i < 2; i++) {
                mma_bf16(acc[i][j], ah[i], bh0, bh1);
                mma_bf16(acc[i][j], ah[i], bl0, bl1);
                mma_bf16(acc[i][j], al[i], bh0, bh1);
            }
        }
        __syncthreads();
    }

    const int g = lane >> 2;
    #pragma unroll
    for (int j = 0; j < 4; j++) {
        const int col = bn + wn + j * 8 + 2 * t;
        const float bv0 = bias[col];
        const float bv1 = bias[col + 1];
        #pragma unroll
        for (int i = 0; i < 2; i++) {
            const int row0 = bm + wm + i * 16 + g;
            float2 v0 = make_float2(acc[i][j][0] + bv0, acc[i][j][1] + bv1);
            float2 v1 = make_float2(acc[i][j][2] + bv0, acc[i][j][3] + bv1);
            *(float2*)(C + (size_t)row0 * N + col)       = v0;
            *(float2*)(C + (size_t)(row0 + 8) * N + col) = v1;
        }
    }
}

// ---------------------------------------------------------------------------
// pk path (unchanged)
// ---------------------------------------------------------------------------
__global__ void pk_init(const float* __restrict__ bk, float* __restrict__ pk)
{
    int i = blockIdx.x * 256 + threadIdx.x;
    if (i < NREL * DD) pk[i] = bk[i & (DD - 1)];
}

__global__ __launch_bounds__(256) void pk_gemm_split(
    const float* __restrict__ pos_emb, const float* __restrict__ Wk,
    float* __restrict__ pk)
{
    __shared__ float pe_s[NREL][128];
    const int n  = blockIdx.x * 256 + threadIdx.x;
    const int k0 = blockIdx.y * 128;

    for (int i = threadIdx.x; i < NREL * 128; i += 256) {
        int r = i >> 7, kk = i & 127;
        pe_s[r][kk] = pos_emb[r * DD + k0 + kk];
    }
    __syncthreads();

    float acc[NREL];
    #pragma unroll
    for (int r = 0; r < NREL; r++) acc[r] = 0.f;

    #pragma unroll 4
    for (int kk = 0; kk < 128; kk++) {
        float w = Wk[(size_t)(k0 + kk) * DD + n];
        #pragma unroll
        for (int r = 0; r < NREL; r++) acc[r] += pe_s[r][kk] * w;
    }
    #pragma unroll
    for (int r = 0; r < NREL; r++)
        atomicAdd(&pk[r * DD + n], acc[r]);
}

// ---------------------------------------------------------------------------
// Tensor-core flash attention with TransformerXL relative bias (proven R5/R7).
// ---------------------------------------------------------------------------
#define KSTR 72
#define TILE_B (64 * KSTR * 2)

#define QH_OFF   0
#define QL_OFF   (QH_OFF + TILE_B)
#define KH_OFF   (QL_OFF + TILE_B)
#define KL_OFF   (KH_OFF + TILE_B)
#define VH_OFF   (KL_OFF + TILE_B)
#define VL_OFF   (VH_OFF + TILE_B)
#define SMALL_OFF (VL_OFF + TILE_B)
#define PKS_OFF  (SMALL_OFF + 64*8*4)
#define US_OFF   (PKS_OFF + NREL*64*4)
#define CORR_OFF (US_OFF + 64*4)
#define AT_SMEM  (CORR_OFF + 32)

__global__ __launch_bounds__(128, 2) void attn_mma(
    const float* __restrict__ q, const float* __restrict__ k,
    const float* __restrict__ v, const float* __restrict__ pk,
    const float* __restrict__ cbias, const float* __restrict__ rbias,
    float* __restrict__ out)
{
    extern __shared__ char smraw[];
    __nv_bfloat16* Qh = (__nv_bfloat16*)(smraw + QH_OFF);
    __nv_bfloat16* Ql = (__nv_bfloat16*)(smraw + QL_OFF);
    __nv_bfloat16* Kh = (__nv_bfloat16*)(smraw + KH_OFF);
    __nv_bfloat16* Kl = (__nv_bfloat16*)(smraw + KL_OFF);
    float* smalls = (float*)(smraw + SMALL_OFF);
    float* pks    = (float*)(smraw + PKS_OFF);
    float* us     = (float*)(smraw + US_OFF);
    float* corr   = (float*)(smraw + CORR_OFF);

    const int tid  = threadIdx.x;
    const int warp = tid >> 5;
    const int lane = tid & 31;
    const int g    = lane >> 2;
    const int t    = lane & 3;
    const int wm   = warp * 16;
    const int h    = blockIdx.y;
    const int b    = blockIdx.z;
    const int q0   = blockIdx.x * 64;

    const float* qb = q + (size_t)b * TT * (HH * DH) + h * DH;
    const float* kb = k + (size_t)b * TT * (HH * DH) + h * DH;
    const float* vb = v + (size_t)b * TT * (HH * DH) + h * DH;

    if (tid < 64) us[tid] = cbias[h * DH + tid];
    for (int i = tid; i < NREL * 64; i += 128) {
        int r = i >> 6, d = i & 63;
        pks[i] = pk[r * DD + h * DH + d];
    }
    __syncthreads();

    #pragma unroll
    for (int it = 0; it < 8; it++) {
        int l = tid + it * 128;
        int row = l >> 4;
        int d4 = (l & 15) << 2;
        float4 vq = *(const float4*)(qb + (size_t)(q0 + row) * (HH * DH) + d4);
        vq.x += us[d4 + 0]; vq.y += us[d4 + 1];
        vq.z += us[d4 + 2]; vq.w += us[d4 + 3];
        uint32_t h01, l01, h23, l23;
        split2_bf16(vq.x, vq.y, h01, l01);
        split2_bf16(vq.z, vq.w, h23, l23);
        *(uint32_t*)&Qh[row * KSTR + d4]     = h01;
        *(uint32_t*)&Qh[row * KSTR + d4 + 2] = h23;
        *(uint32_t*)&Ql[row * KSTR + d4]     = l01;
        *(uint32_t*)&Ql[row * KSTR + d4 + 2] = l23;
    }
    if (tid < NREL) {
        float s = 0.f;
        for (int d = 0; d < 64; d++)
            s += (rbias[h * DH + d] - us[d]) * pks[tid * 64 + d];
        corr[tid] = s;
    }
    __syncthreads();

    if (tid < 64) {
        float accr[NREL];
        #pragma unroll
        for (int r = 0; r < NREL; r++) accr[r] = corr[r];
        for (int d = 0; d < 64; d++) {
            float qv = __bfloat162float(Qh[tid * KSTR + d]) +
                       __bfloat162float(Ql[tid * KSTR + d]);
            #pragma unroll
            for (int r = 0; r < NREL; r++) accr[r] += qv * pks[r * 64 + d];
        }
        #pragma unroll
        for (int r = 0; r < NREL; r++) smalls[tid * 8 + r] = accr[r];
    }

    uint32_t qfh[4][4], qfl[4][4];
    #pragma unroll
    for (int ks = 0; ks < 4; ks++) {
        int d0 = 16 * ks + 2 * t;
        qfh[ks][0] = *(uint32_t*)&Qh[(wm + g) * KSTR + d0];
        qfh[ks][1] = *(uint32_t*)&Qh[(wm + g + 8) * KSTR + d0];
        qfh[ks][2] = *(uint32_t*)&Qh[(wm + g) * KSTR + d0 + 8];
        qfh[ks][3] = *(uint32_t*)&Qh[(wm + g + 8) * KSTR + d0 + 8];
        qfl[ks][0] = *(uint32_t*)&Ql[(wm + g) * KSTR + d0];
        qfl[ks][1] = *(uint32_t*)&Ql[(wm + g + 8) * KSTR + d0];
        qfl[ks][2] = *(uint32_t*)&Ql[(wm + g) * KSTR + d0 + 8];
        qfl[ks][3] = *(uint32_t*)&Ql[(wm + g + 8) * KSTR + d0 + 8];
    }

    const uint32_t vh_base = (uint32_t)__cvta_generic_to_shared(smraw + VH_OFF);
    const uint32_t vl_base = (uint32_t)__cvta_generic_to_shared(smraw + VL_OFF);
    const int lm = lane & 15;
    const uint32_t vh_lane = vh_base + (uint32_t)lm * (KSTR * 2);
    const uint32_t vl_lane = vl_base + (uint32_t)lm * (KSTR * 2);

    __nv_bfloat16* Vh = (__nv_bfloat16*)(smraw + VH_OFF);
    __nv_bfloat16* Vl = (__nv_bfloat16*)(smraw + VL_OFF);

    float m0 = -1e30f, m1 = -1e30f, l0 = 0.f, l1 = 0.f;
    float O[8][4];
    #pragma unroll
    for (int jd = 0; jd < 8; jd++)
        #pragma unroll
        for (int r = 0; r < 4; r++) O[jd][r] = 0.f;

    const float scale = 0.125f;
    const int tq0 = q0 + wm + g;
    const int rl0 = wm + g;

    for (int kt = 0; kt < TT; kt += 64) {
        __syncthreads();
        #pragma unroll
        for (int it = 0; it < 8; it++) {
            int l = tid + it * 128;
            int key = l >> 4;
            int d4 = (l & 15) << 2;
            float4 kv4 = *(const float4*)(kb + (size_t)(kt + key) * (HH * DH) + d4);
            uint32_t h01, l01, h23, l23;
            split2_bf16(kv4.x, kv4.y, h01, l01);
            split2_bf16(kv4.z, kv4.w, h23, l23);
            *(uint32_t*)&Kh[key * KSTR + d4]     = h01;
            *(uint32_t*)&Kh[key * KSTR + d4 + 2] = h23;
            *(uint32_t*)&Kl[key * KSTR + d4]     = l01;
            *(uint32_t*)&Kl[key * KSTR + d4 + 2] = l23;
            float4 vv4 = *(const float4*)(vb + (size_t)(kt + key) * (HH * DH) + d4);
            split2_bf16(vv4.x, vv4.y, h01, l01);
            split2_bf16(vv4.z, vv4.w, h23, l23);
            *(uint32_t*)&Vh[key * KSTR + d4]     = h01;
            *(uint32_t*)&Vh[key * KSTR + d4 + 2] = h23;
            *(uint32_t*)&Vl[key * KSTR + d4]     = l01;
            *(uint32_t*)&Vl[key * KSTR + d4 + 2] = l23;
        }
        __syncthreads();

        float S[8][4];
        #pragma unroll
        for (int j = 0; j < 8; j++)
            #pragma unroll
            for (int r = 0; r < 4; r++) S[j][r] = 0.f;

        #pragma unroll
        for (int ks = 0; ks < 4; ks++) {
            const int d0 = 16 * ks + 2 * t;
            #pragma unroll
            for (int j = 0; j < 8; j++) {
                const int key = 8 * j + g;
                uint32_t bh0 = *(uint32_t*)&Kh[key * KSTR + d0];
                uint32_t bh1 = *(uint32_t*)&Kh[key * KSTR + d0 + 8];
                uint32_t bl0 = *(uint32_t*)&Kl[key * KSTR + d0];
                uint32_t bl1 = *(uint32_t*)&Kl[key * KSTR + d0 + 8];
                mma_bf16(S[j], qfh[ks], bh0, bh1);
                mma_bf16(S[j], qfh[ks], bl0, bl1);
                mma_bf16(S[j], qfl[ks], bh0, bh1);
            }
        }

        float mx0 = -1e30f, mx1 = -1e30f;
        #pragma unroll
        for (int j = 0; j < 8; j++) {
            #pragma unroll
            for (int c = 0; c < 2; c++) {
                int tk = kt + 8 * j + 2 * t + c;
                int d0 = min(3, max(-3, tq0 - tk)) + 3;
                int d1 = min(3, max(-3, tq0 + 8 - tk)) + 3;
                S[j][c]     = (S[j][c]     + smalls[rl0 * 8 + d0]) * scale;
                S[j][2 + c] = (S[j][2 + c] + smalls[(rl0 + 8) * 8 + d1]) * scale;
                mx0 = fmaxf(mx0, S[j][c]);
                mx1 = fmaxf(mx1, S[j][2 + c]);
            }
        }
        mx0 = fmaxf(mx0, __shfl_xor_sync(0xffffffffu, mx0, 1));
        mx0 = fmaxf(mx0, __shfl_xor_sync(0xffffffffu, mx0, 2));
        mx1 = fmaxf(mx1, __shfl_xor_sync(0xffffffffu, mx1, 1));
        mx1 = fmaxf(mx1, __shfl_xor_sync(0xffffffffu, mx1, 2));

        float mn0 = fmaxf(m0, mx0), mn1 = fmaxf(m1, mx1);
        float cr0 = __expf(m0 - mn0), cr1 = __expf(m1 - mn1);
        m0 = mn0; m1 = mn1;

        uint32_t phA[8], plA[8], phB[8], plB[8];
        float s0 = 0.f, s1 = 0.f;
        #pragma unroll
        for (int j = 0; j < 8; j++) {
            float p0 = __expf(S[j][0] - mn0);
            float p1 = __expf(S[j][1] - mn0);
            float p2 = __expf(S[j][2] - mn1);
            float p3 = __expf(S[j][3] - mn1);
            s0 += p0 + p1; s1 += p2 + p3;
            split2_bf16(p0, p1, phA[j], plA[j]);
            split2_bf16(p2, p3, phB[j], plB[j]);
        }
        s0 += __shfl_xor_sync(0xffffffffu, s0, 1);
        s0 += __shfl_xor_sync(0xffffffffu, s0, 2);
        s1 += __shfl_xor_sync(0xffffffffu, s1, 1);
        s1 += __shfl_xor_sync(0xffffffffu, s1, 2);
        l0 = l0 * cr0 + s0;
        l1 = l1 * cr1 + s1;

        #pragma unroll
        for (int jd = 0; jd < 8; jd++) {
            O[jd][0] *= cr0; O[jd][1] *= cr0;
            O[jd][2] *= cr1; O[jd][3] *= cr1;
        }

        #pragma unroll
        for (int kv = 0; kv < 4; kv++) {
            uint32_t ah[4] = { phA[2*kv], phB[2*kv], phA[2*kv+1], phB[2*kv+1] };
            uint32_t al[4] = { plA[2*kv], plB[2*kv], plA[2*kv+1], plB[2*kv+1] };
            const uint32_t rh = vh_lane + (uint32_t)kv * 16 * (KSTR * 2);
            const uint32_t rl = vl_lane + (uint32_t)kv * 16 * (KSTR * 2);
            #pragma unroll
            for (int jd = 0; jd < 8; jd++) {
                uint32_t bh0, bh1, bl0, bl1;
                ldsm_x2_t(bh0, bh1, rh + jd * 16);
                ldsm_x2_t(bl0, bl1, rl + jd * 16);
                mma_bf16(O[jd], ah, bh0, bh1);
                mma_bf16(O[jd], ah, bl0, bl1);
                mma_bf16(O[jd], al, bh0, bh1);
            }
        }
    }

    float inv0 = 1.f / l0, inv1 = 1.f / l1;
    #pragma unroll
    for (int jd = 0; jd < 8; jd++) {
        int col = h * DH + 8 * jd + 2 * t;
        float2 o0 = make_float2(O[jd][0] * inv0, O[jd][1] * inv0);
        float2 o1 = make_float2(O[jd][2] * inv1, O[jd][3] * inv1);
        *(float2*)(out + ((size_t)b * TT + tq0) * (HH * DH) + col)     = o0;
        *(float2*)(out + ((size_t)b * TT + tq0 + 8) * (HH * DH) + col) = o1;
    }
}

// ---------------------------------------------------------------------------
extern "C" void kernel_launch(void* const* d_in, const int* in_sizes, int n_in,
                              void* d_out, int out_size)
{
    const float* query   = (const float*)d_in[0];
    const float* key_    = (const float*)d_in[1];
    const float* value   = (const float*)d_in[2];
    const float* Wq      = (const float*)d_in[3];
    const float* bq      = (const float*)d_in[4];
    const float* Wk      = (const float*)d_in[5];
    const float* bk      = (const float*)d_in[6];
    const float* Wv      = (const float*)d_in[7];
    const float* bv      = (const float*)d_in[8];
    const float* Wo      = (const float*)d_in[9];
    const float* bo      = (const float*)d_in[10];
    const float* cbias   = (const float*)d_in[11];
    const float* rbias   = (const float*)d_in[12];
    const float* pos_emb = (const float*)d_in[13];

    float *q, *k, *v, *attn, *pk;
    cudaGetSymbolAddress((void**)&q, g_q);
    cudaGetSymbolAddress((void**)&k, g_k);
    cudaGetSymbolAddress((void**)&v, g_v);
    cudaGetSymbolAddress((void**)&attn, g_attn);
    cudaGetSymbolAddress((void**)&pk, g_pk);

    __nv_bfloat16 *wqh, *wql, *wkh, *wkl, *wvh, *wvl, *woh, *wol;
    __nv_bfloat16 *xh, *xl, *yh, *yl, *zh, *zl, *ath, *atl;
    cudaGetSymbolAddress((void**)&wqh, g_wq_h); cudaGetSymbolAddress((void**)&wql, g_wq_l);
    cudaGetSymbolAddress((void**)&wkh, g_wk_h); cudaGetSymbolAddress((void**)&wkl, g_wk_l);
    cudaGetSymbolAddress((void**)&wvh, g_wv_h); cudaGetSymbolAddress((void**)&wvl, g_wv_l);
    cudaGetSymbolAddress((void**)&woh, g_wo_h); cudaGetSymbolAddress((void**)&wol, g_wo_l);
    cudaGetSymbolAddress((void**)&xh, g_x_h);   cudaGetSymbolAddress((void**)&xl, g_x_l);
    cudaGetSymbolAddress((void**)&yh, g_y_h);   cudaGetSymbolAddress((void**)&yl, g_y_l);
    cudaGetSymbolAddress((void**)&zh, g_z_h);   cudaGetSymbolAddress((void**)&zl, g_z_l);
    cudaGetSymbolAddress((void**)&ath, g_a_h);  cudaGetSymbolAddress((void**)&atl, g_a_l);

    const int M = BB * TT;     // 4096
    const int N = HH * DH;     // 1024
    const int K = DD;          // 1024

    const int wn4 = DD * HH * DH / 4;     // 262144
    const int an4 = BB * TT * DD / 4;     // 1048576
    pack_bf16<<<wn4 / 256, 256>>>(Wq, wqh, wql, wn4);
    pack_bf16<<<wn4 / 256, 256>>>(Wk, wkh, wkl, wn4);
    pack_bf16<<<wn4 / 256, 256>>>(Wv, wvh, wvl, wn4);
    pack_bf16<<<wn4 / 256, 256>>>(Wo, woh, wol, wn4);
    pack_bf16<<<an4 / 256, 256>>>(query, xh, xl, an4);
    pack_bf16<<<an4 / 256, 256>>>(key_,  yh, yl, an4);
    pack_bf16<<<an4 / 256, 256>>>(value, zh, zl, an4);

    dim3 gg(N / 128, M / 64);  // (8, 64)
    gemm_bf16p<<<gg, 256>>>(xh, xl, wqh, wql, bq, q, M, N, K);
    gemm_bf16p<<<gg, 256>>>(yh, yl, wkh, wkl, bk, k, M, N, K);
    gemm_bf16p<<<gg, 256>>>(zh, zl, wvh, wvl, bv, v, M, N, K);

    pk_init<<<(NREL * DD + 255) / 256, 256>>>(bk, pk);
    pk_gemm_split<<<dim3(DD / 256, DD / 128), 256>>>(pos_emb, Wk, pk);

    cudaFuncSetAttribute(attn_mma,
                         cudaFuncAttributeMaxDynamicSharedMemorySize, AT_SMEM);
    attn_mma<<<dim3(TT / 64, HH, BB), 128, AT_SMEM>>>(q, k, v, pk,
                                                      cbias, rbias, attn);

    pack_bf16<<<an4 / 256, 256>>>(attn, ath, atl, an4);
    gemm_bf16p<<<gg, 256>>>(ath, atl, woh, wol, bo, (float*)d_out, M, N, K);
}

// round 12
// speedup vs baseline: 4.7463x; 1.0877x over previous
#include <cuda_runtime.h>
#include <cuda_bf16.h>
#include <math.h>
#include <stdint.h>

#define BB 2
#define TT 2048
#define DD 1024
#define HH 16
#define DH 64
#define NREL 7

// Scratch (static device globals — no allocation)
__device__ float g_q[BB*TT*HH*DH];
__device__ float g_k[BB*TT*HH*DH];
__device__ float g_v[BB*TT*HH*DH];
__device__ float g_pk[NREL*HH*DH];

// packed bf16 hi/lo planes (all layout-preserving: W [K][N], acts [M][K])
__device__ __nv_bfloat16 g_wq_h[DD*HH*DH], g_wq_l[DD*HH*DH];
__device__ __nv_bfloat16 g_wk_h[DD*HH*DH], g_wk_l[DD*HH*DH];
__device__ __nv_bfloat16 g_wv_h[DD*HH*DH], g_wv_l[DD*HH*DH];
__device__ __nv_bfloat16 g_wo_h[DD*HH*DH], g_wo_l[DD*HH*DH];
__device__ __nv_bfloat16 g_x_h[BB*TT*DD],  g_x_l[BB*TT*DD];   // query
__device__ __nv_bfloat16 g_y_h[BB*TT*DD],  g_y_l[BB*TT*DD];   // key
__device__ __nv_bfloat16 g_z_h[BB*TT*DD],  g_z_l[BB*TT*DD];   // value
__device__ __nv_bfloat16 g_a_h[BB*TT*DD],  g_a_l[BB*TT*DD];   // attn out

// ---------------------------------------------------------------------------
// helpers
// ---------------------------------------------------------------------------
__device__ __forceinline__ void cp16s(uint32_t saddr, const void* gmem) {
    asm volatile("cp.async.ca.shared.global [%0], [%1], 16;\n" :: "r"(saddr), "l"(gmem));
}
__device__ __forceinline__ void cp_commit() {
    asm volatile("cp.async.commit_group;\n");
}
__device__ __forceinline__ void cp_wait1() {
    asm volatile("cp.async.wait_group 1;\n");
}
__device__ __forceinline__ void cp_wait0() {
    asm volatile("cp.async.wait_group 0;\n");
}

__device__ __forceinline__ void mma_bf16(float* c, const uint32_t* a,
                                         uint32_t b0, uint32_t b1) {
    asm volatile(
        "mma.sync.aligned.m16n8k16.row.col.f32.bf16.bf16.f32 "
        "{%0,%1,%2,%3}, {%4,%5,%6,%7}, {%8,%9}, {%0,%1,%2,%3};"
        : "+f"(c[0]), "+f"(c[1]), "+f"(c[2]), "+f"(c[3])
        : "r"(a[0]), "r"(a[1]), "r"(a[2]), "r"(a[3]), "r"(b0), "r"(b1));
}

__device__ __forceinline__ void ldsm_x2_t(uint32_t& r0, uint32_t& r1, uint32_t addr) {
    asm volatile("ldmatrix.sync.aligned.m8n8.x2.trans.shared.b16 {%0,%1}, [%2];"
                 : "=r"(r0), "=r"(r1) : "r"(addr));
}
__device__ __forceinline__ void ldsm_x4(uint32_t* r, uint32_t addr) {
    asm volatile("ldmatrix.sync.aligned.m8n8.x4.shared.b16 {%0,%1,%2,%3}, [%4];"
                 : "=r"(r[0]), "=r"(r[1]), "=r"(r[2]), "=r"(r[3]) : "r"(addr));
}

// pack two floats into bf16x2 hi word + bf16x2 residual word
__device__ __forceinline__ void split2_bf16(float x0, float x1,
                                            uint32_t& hi, uint32_t& lo) {
    __nv_bfloat16 h0 = __float2bfloat16_rn(x0);
    __nv_bfloat16 h1 = __float2bfloat16_rn(x1);
    float r0 = x0 - __bfloat162float(h0);
    float r1 = x1 - __bfloat162float(h1);
    __nv_bfloat162 H = __halves2bfloat162(h0, h1);
    __nv_bfloat162 L = __halves2bfloat162(__float2bfloat16_rn(r0),
                                          __float2bfloat16_rn(r1));
    hi = *(uint32_t*)&H;
    lo = *(uint32_t*)&L;
}

// ---------------------------------------------------------------------------
// pack fp32 -> bf16 hi/lo planes (layout preserved)
// ---------------------------------------------------------------------------
__global__ __launch_bounds__(256) void pack_bf16(
    const float* __restrict__ src, __nv_bfloat16* __restrict__ hi,
    __nv_bfloat16* __restrict__ lo, int n4)
{
    int i = blockIdx.x * 256 + threadIdx.x;
    if (i < n4) {
        float4 v = ((const float4*)src)[i];
        uint32_t h01, l01, h23, l23;
        split2_bf16(v.x, v.y, h01, l01);
        split2_bf16(v.z, v.w, h23, l23);
        ((uint2*)hi)[i] = make_uint2(h01, h23);
        ((uint2*)lo)[i] = make_uint2(l01, l23);
    }
}

// ---------------------------------------------------------------------------
// packed-bf16 3-term mma GEMM v2: C[M,N] = A@W + bias.
// BM=128, BN=128, BK=32, 256 threads (8 warps = 4m x 2n), warp tile 32x64.
// 96 HMMA per warp per barrier period (matches the attention kernel's profile).
// 2-stage cp.async, ldmatrix fragments. A:[M][K] hi/lo, W:[K][N] hi/lo.
// ---------------------------------------------------------------------------
#define AP2 40      // bf16/row for A (80B; 8-row phases hit distinct 16B groups)
#define BP2 136     // bf16/row for B (272B == 16 mod 128; trans-ldmatrix clean)
#define A_PLANE2 (128 * AP2 * 2)            // 10240 B
#define B_PLANE2 (32 * BP2 * 2)             // 8704 B
#define STAGE2   (2 * A_PLANE2 + 2 * B_PLANE2)  // 37888 B
#define G2_SMEM  (2 * STAGE2)               // 75776 B

__global__ __launch_bounds__(256, 2) void gemm_bf16p2(
    const __nv_bfloat16* __restrict__ Ah_g, const __nv_bfloat16* __restrict__ Al_g,
    const __nv_bfloat16* __restrict__ Bh_g, const __nv_bfloat16* __restrict__ Bl_g,
    const float* __restrict__ bias, float* __restrict__ C,
    int M, int N, int K)
{
    extern __shared__ char smraw[];
    const uint32_t sb0 = (uint32_t)__cvta_generic_to_shared(smraw);

    const int tid  = threadIdx.x;
    const int warp = tid >> 5;
    const int lane = tid & 31;
    const int t    = lane & 3;
    const int g    = lane >> 2;
    const int lm   = lane & 15;
    const int lq   = lane >> 4;
    const int wm   = (warp & 3) * 32;      // 4 m-groups
    const int wn   = (warp >> 2) * 64;     // 2 n-groups
    const int bm   = blockIdx.y * 128;
    const int bn   = blockIdx.x * 128;
    const int NIT  = K >> 5;               // 32

    // fill chunk c (k0 = c*32) into stage s. 2048 16B units, 8 per thread.
    auto fill = [&](int c, int s) {
        const int k0 = c * 32;
        const uint32_t st = sb0 + s * STAGE2;
        #pragma unroll
        for (int u = 0; u < 8; u++) {
            int id = tid + u * 256;          // 0..2047
            int plane = id >> 9;             // 0:Ah 1:Al 2:Bh 3:Bl
            int wi = id & 511;
            if (plane < 2) {
                int row = wi >> 2;           // 0..127
                int c8  = (wi & 3) * 8;      // 0,8,16,24
                const __nv_bfloat16* src = (plane == 0) ? Ah_g : Al_g;
                uint32_t dst = st + plane * A_PLANE2 +
                               (uint32_t)(row * AP2 + c8) * 2;
                cp16s(dst, src + (size_t)(bm + row) * K + k0 + c8);
            } else {
                int krow = wi >> 4;          // 0..31
                int c8   = (wi & 15) * 8;    // 0..120
                const __nv_bfloat16* src = (plane == 2) ? Bh_g : Bl_g;
                uint32_t dst = st + 2 * A_PLANE2 + (plane - 2) * B_PLANE2 +
                               (uint32_t)(krow * BP2 + c8) * 2;
                cp16s(dst, src + (size_t)(k0 + krow) * N + bn + c8);
            }
        }
        cp_commit();
    };

    fill(0, 0);
    fill(1, 1);

    float acc[2][8][4];
    #pragma unroll
    for (int i = 0; i < 2; i++)
        #pragma unroll
        for (int j = 0; j < 8; j++)
            #pragma unroll
            for (int r = 0; r < 4; r++) acc[i][j][r] = 0.f;

    for (int it = 0; it < NIT; it++) {
        const int s = it & 1;
        if (it + 2 < NIT) cp_wait1(); else cp_wait0();
        __syncthreads();

        const uint32_t st = sb0 + s * STAGE2;
        const uint32_t ah_base = st;
        const uint32_t al_base = st + A_PLANE2;
        const uint32_t bh_base = st + 2 * A_PLANE2;
        const uint32_t bl_base = st + 2 * A_PLANE2 + B_PLANE2;

        #pragma unroll
        for (int ks = 0; ks < 2; ks++) {
            uint32_t ah[2][4], al[2][4];
            #pragma unroll
            for (int i = 0; i < 2; i++) {
                uint32_t off = (uint32_t)((wm + i * 16 + lm) * AP2) * 2 +
                               lq * 16 + ks * 32;
                ldsm_x4(ah[i], ah_base + off);
                ldsm_x4(al[i], al_base + off);
            }
            #pragma unroll
            for (int j = 0; j < 8; j++) {
                uint32_t boff = (uint32_t)((ks * 16 + lm) * BP2) * 2 +
                                (uint32_t)(wn + j * 8) * 2;
                uint32_t bh0, bh1, bl0, bl1;
                ldsm_x2_t(bh0, bh1, bh_base + boff);
                ldsm_x2_t(bl0, bl1, bl_base + boff);
                #pragma unroll
                for (int i = 0; i < 2; i++) {
                    mma_bf16(acc[i][j], ah[i], bh0, bh1);
                    mma_bf16(acc[i][j], ah[i], bl0, bl1);
                    mma_bf16(acc[i][j], al[i], bh0, bh1);
                }
            }
        }
        __syncthreads();
        if (it + 2 < NIT) fill(it + 2, s);
    }

    // epilogue: bias + store
    #pragma unroll
    for (int j = 0; j < 8; j++) {
        const int col = bn + wn + j * 8 + 2 * t;
        const float bv0 = bias[col];
        const float bv1 = bias[col + 1];
        #pragma unroll
        for (int i = 0; i < 2; i++) {
            const int row0 = bm + wm + i * 16 + g;
            float2 v0 = make_float2(acc[i][j][0] + bv0, acc[i][j][1] + bv1);
            float2 v1 = make_float2(acc[i][j][2] + bv0, acc[i][j][3] + bv1);
            *(float2*)(C + (size_t)row0 * N + col)       = v0;
            *(float2*)(C + (size_t)(row0 + 8) * N + col) = v1;
        }
    }
}

// ---------------------------------------------------------------------------
// pk path (unchanged)
// ---------------------------------------------------------------------------
__global__ void pk_init(const float* __restrict__ bk, float* __restrict__ pk)
{
    int i = blockIdx.x * 256 + threadIdx.x;
    if (i < NREL * DD) pk[i] = bk[i & (DD - 1)];
}

__global__ __launch_bounds__(256) void pk_gemm_split(
    const float* __restrict__ pos_emb, const float* __restrict__ Wk,
    float* __restrict__ pk)
{
    __shared__ float pe_s[NREL][128];
    const int n  = blockIdx.x * 256 + threadIdx.x;
    const int k0 = blockIdx.y * 128;

    for (int i = threadIdx.x; i < NREL * 128; i += 256) {
        int r = i >> 7, kk = i & 127;
        pe_s[r][kk] = pos_emb[r * DD + k0 + kk];
    }
    __syncthreads();

    float acc[NREL];
    #pragma unroll
    for (int r = 0; r < NREL; r++) acc[r] = 0.f;

    #pragma unroll 4
    for (int kk = 0; kk < 128; kk++) {
        float w = Wk[(size_t)(k0 + kk) * DD + n];
        #pragma unroll
        for (int r = 0; r < NREL; r++) acc[r] += pe_s[r][kk] * w;
    }
    #pragma unroll
    for (int r = 0; r < NREL; r++)
        atomicAdd(&pk[r * DD + n], acc[r]);
}

// ---------------------------------------------------------------------------
// Tensor-core flash attention with TransformerXL relative bias (proven R5-R10);
// epilogue writes bf16 hi/lo planes directly (feeds the packed out-proj GEMM).
// ---------------------------------------------------------------------------
#define KSTR 72
#define TILE_B (64 * KSTR * 2)

#define QH_OFF   0
#define QL_OFF   (QH_OFF + TILE_B)
#define KH_OFF   (QL_OFF + TILE_B)
#define KL_OFF   (KH_OFF + TILE_B)
#define VH_OFF   (KL_OFF + TILE_B)
#define VL_OFF   (VH_OFF + TILE_B)
#define SMALL_OFF (VL_OFF + TILE_B)
#define PKS_OFF  (SMALL_OFF + 64*8*4)
#define US_OFF   (PKS_OFF + NREL*64*4)
#define CORR_OFF (US_OFF + 64*4)
#define AT_SMEM  (CORR_OFF + 32)

__global__ __launch_bounds__(128, 2) void attn_mma(
    const float* __restrict__ q, const float* __restrict__ k,
    const float* __restrict__ v, const float* __restrict__ pk,
    const float* __restrict__ cbias, const float* __restrict__ rbias,
    __nv_bfloat16* __restrict__ outh, __nv_bfloat16* __restrict__ outl)
{
    extern __shared__ char smraw[];
    __nv_bfloat16* Qh = (__nv_bfloat16*)(smraw + QH_OFF);
    __nv_bfloat16* Ql = (__nv_bfloat16*)(smraw + QL_OFF);
    __nv_bfloat16* Kh = (__nv_bfloat16*)(smraw + KH_OFF);
    __nv_bfloat16* Kl = (__nv_bfloat16*)(smraw + KL_OFF);
    float* smalls = (float*)(smraw + SMALL_OFF);
    float* pks    = (float*)(smraw + PKS_OFF);
    float* us     = (float*)(smraw + US_OFF);
    float* corr   = (float*)(smraw + CORR_OFF);

    const int tid  = threadIdx.x;
    const int warp = tid >> 5;
    const int lane = tid & 31;
    const int g    = lane >> 2;
    const int t    = lane & 3;
    const int wm   = warp * 16;
    const int h    = blockIdx.y;
    const int b    = blockIdx.z;
    const int q0   = blockIdx.x * 64;

    const float* qb = q + (size_t)b * TT * (HH * DH) + h * DH;
    const float* kb = k + (size_t)b * TT * (HH * DH) + h * DH;
    const float* vb = v + (size_t)b * TT * (HH * DH) + h * DH;

    if (tid < 64) us[tid] = cbias[h * DH + tid];
    for (int i = tid; i < NREL * 64; i += 128) {
        int r = i >> 6, d = i & 63;
        pks[i] = pk[r * DD + h * DH + d];
    }
    __syncthreads();

    #pragma unroll
    for (int it = 0; it < 8; it++) {
        int l = tid + it * 128;
        int row = l >> 4;
        int d4 = (l & 15) << 2;
        float4 vq = *(const float4*)(qb + (size_t)(q0 + row) * (HH * DH) + d4);
        vq.x += us[d4 + 0]; vq.y += us[d4 + 1];
        vq.z += us[d4 + 2]; vq.w += us[d4 + 3];
        uint32_t h01, l01, h23, l23;
        split2_bf16(vq.x, vq.y, h01, l01);
        split2_bf16(vq.z, vq.w, h23, l23);
        *(uint32_t*)&Qh[row * KSTR + d4]     = h01;
        *(uint32_t*)&Qh[row * KSTR + d4 + 2] = h23;
        *(uint32_t*)&Ql[row * KSTR + d4]     = l01;
        *(uint32_t*)&Ql[row * KSTR + d4 + 2] = l23;
    }
    if (tid < NREL) {
        float s = 0.f;
        for (int d = 0; d < 64; d++)
            s += (rbias[h * DH + d] - us[d]) * pks[tid * 64 + d];
        corr[tid] = s;
    }
    __syncthreads();

    if (tid < 64) {
        float accr[NREL];
        #pragma unroll
        for (int r = 0; r < NREL; r++) accr[r] = corr[r];
        for (int d = 0; d < 64; d++) {
            float qv = __bfloat162float(Qh[tid * KSTR + d]) +
                       __bfloat162float(Ql[tid * KSTR + d]);
            #pragma unroll
            for (int r = 0; r < NREL; r++) accr[r] += qv * pks[r * 64 + d];
        }
        #pragma unroll
        for (int r = 0; r < NREL; r++) smalls[tid * 8 + r] = accr[r];
    }

    uint32_t qfh[4][4], qfl[4][4];
    #pragma unroll
    for (int ks = 0; ks < 4; ks++) {
        int d0 = 16 * ks + 2 * t;
        qfh[ks][0] = *(uint32_t*)&Qh[(wm + g) * KSTR + d0];
        qfh[ks][1] = *(uint32_t*)&Qh[(wm + g + 8) * KSTR + d0];
        qfh[ks][2] = *(uint32_t*)&Qh[(wm + g) * KSTR + d0 + 8];
        qfh[ks][3] = *(uint32_t*)&Qh[(wm + g + 8) * KSTR + d0 + 8];
        qfl[ks][0] = *(uint32_t*)&Ql[(wm + g) * KSTR + d0];
        qfl[ks][1] = *(uint32_t*)&Ql[(wm + g + 8) * KSTR + d0];
        qfl[ks][2] = *(uint32_t*)&Ql[(wm + g) * KSTR + d0 + 8];
        qfl[ks][3] = *(uint32_t*)&Ql[(wm + g + 8) * KSTR + d0 + 8];
    }

    const uint32_t vh_base = (uint32_t)__cvta_generic_to_shared(smraw + VH_OFF);
    const uint32_t vl_base = (uint32_t)__cvta_generic_to_shared(smraw + VL_OFF);
    const int lm = lane & 15;
    const uint32_t vh_lane = vh_base + (uint32_t)lm * (KSTR * 2);
    const uint32_t vl_lane = vl_base + (uint32_t)lm * (KSTR * 2);

    __nv_bfloat16* Vh = (__nv_bfloat16*)(smraw + VH_OFF);
    __nv_bfloat16* Vl = (__nv_bfloat16*)(smraw + VL_OFF);

    float m0 = -1e30f, m1 = -1e30f, l0 = 0.f, l1 = 0.f;
    float O[8][4];
    #pragma unroll
    for (int jd = 0; jd < 8; jd++)
        #pragma unroll
        for (int r = 0; r < 4; r++) O[jd][r] = 0.f;

    const float scale = 0.125f;
    const int tq0 = q0 + wm + g;
    const int rl0 = wm + g;

    for (int kt = 0; kt < TT; kt += 64) {
        __syncthreads();
        #pragma unroll
        for (int it = 0; it < 8; it++) {
            int l = tid + it * 128;
            int key = l >> 4;
            int d4 = (l & 15) << 2;
            float4 kv4 = *(const float4*)(kb + (size_t)(kt + key) * (HH * DH) + d4);
            uint32_t h01, l01, h23, l23;
            split2_bf16(kv4.x, kv4.y, h01, l01);
            split2_bf16(kv4.z, kv4.w, h23, l23);
            *(uint32_t*)&Kh[key * KSTR + d4]     = h01;
            *(uint32_t*)&Kh[key * KSTR + d4 + 2] = h23;
            *(uint32_t*)&Kl[key * KSTR + d4]     = l01;
            *(uint32_t*)&Kl[key * KSTR + d4 + 2] = l23;
            float4 vv4 = *(const float4*)(vb + (size_t)(kt + key) * (HH * DH) + d4);
            split2_bf16(vv4.x, vv4.y, h01, l01);
            split2_bf16(vv4.z, vv4.w, h23, l23);
            *(uint32_t*)&Vh[key * KSTR + d4]     = h01;
            *(uint32_t*)&Vh[key * KSTR + d4 + 2] = h23;
            *(uint32_t*)&Vl[key * KSTR + d4]     = l01;
            *(uint32_t*)&Vl[key * KSTR + d4 + 2] = l23;
        }
        __syncthreads();

        float S[8][4];
        #pragma unroll
        for (int j = 0; j < 8; j++)
            #pragma unroll
            for (int r = 0; r < 4; r++) S[j][r] = 0.f;

        #pragma unroll
        for (int ks = 0; ks < 4; ks++) {
            const int d0 = 16 * ks + 2 * t;
            #pragma unroll
            for (int j = 0; j < 8; j++) {
                const int key = 8 * j + g;
                uint32_t bh0 = *(uint32_t*)&Kh[key * KSTR + d0];
                uint32_t bh1 = *(uint32_t*)&Kh[key * KSTR + d0 + 8];
                uint32_t bl0 = *(uint32_t*)&Kl[key * KSTR + d0];
                uint32_t bl1 = *(uint32_t*)&Kl[key * KSTR + d0 + 8];
                mma_bf16(S[j], qfh[ks], bh0, bh1);
                mma_bf16(S[j], qfh[ks], bl0, bl1);
                mma_bf16(S[j], qfl[ks], bh0, bh1);
            }
        }

        float mx0 = -1e30f, mx1 = -1e30f;
        #pragma unroll
        for (int j = 0; j < 8; j++) {
            #pragma unroll
            for (int c = 0; c < 2; c++) {
                int tk = kt + 8 * j + 2 * t + c;
                int d0 = min(3, max(-3, tq0 - tk)) + 3;
                int d1 = min(3, max(-3, tq0 + 8 - tk)) + 3;
                S[j][c]     = (S[j][c]     + smalls[rl0 * 8 + d0]) * scale;
                S[j][2 + c] = (S[j][2 + c] + smalls[(rl0 + 8) * 8 + d1]) * scale;
                mx0 = fmaxf(mx0, S[j][c]);
                mx1 = fmaxf(mx1, S[j][2 + c]);
            }
        }
        mx0 = fmaxf(mx0, __shfl_xor_sync(0xffffffffu, mx0, 1));
        mx0 = fmaxf(mx0, __shfl_xor_sync(0xffffffffu, mx0, 2));
        mx1 = fmaxf(mx1, __shfl_xor_sync(0xffffffffu, mx1, 1));
        mx1 = fmaxf(mx1, __shfl_xor_sync(0xffffffffu, mx1, 2));

        float mn0 = fmaxf(m0, mx0), mn1 = fmaxf(m1, mx1);
        float cr0 = __expf(m0 - mn0), cr1 = __expf(m1 - mn1);
        m0 = mn0; m1 = mn1;

        uint32_t phA[8], plA[8], phB[8], plB[8];
        float s0 = 0.f, s1 = 0.f;
        #pragma unroll
        for (int j = 0; j < 8; j++) {
            float p0 = __expf(S[j][0] - mn0);
            float p1 = __expf(S[j][1] - mn0);
            float p2 = __expf(S[j][2] - mn1);
            float p3 = __expf(S[j][3] - mn1);
            s0 += p0 + p1; s1 += p2 + p3;
            split2_bf16(p0, p1, phA[j], plA[j]);
            split2_bf16(p2, p3, phB[j], plB[j]);
        }
        s0 += __shfl_xor_sync(0xffffffffu, s0, 1);
        s0 += __shfl_xor_sync(0xffffffffu, s0, 2);
        s1 += __shfl_xor_sync(0xffffffffu, s1, 1);
        s1 += __shfl_xor_sync(0xffffffffu, s1, 2);
        l0 = l0 * cr0 + s0;
        l1 = l1 * cr1 + s1;

        #pragma unroll
        for (int jd = 0; jd < 8; jd++) {
            O[jd][0] *= cr0; O[jd][1] *= cr0;
            O[jd][2] *= cr1; O[jd][3] *= cr1;
        }

        #pragma unroll
        for (int kv = 0; kv < 4; kv++) {
            uint32_t ah[4] = { phA[2*kv], phB[2*kv], phA[2*kv+1], phB[2*kv+1] };
            uint32_t al[4] = { plA[2*kv], plB[2*kv], plA[2*kv+1], plB[2*kv+1] };
            const uint32_t rh = vh_lane + (uint32_t)kv * 16 * (KSTR * 2);
            const uint32_t rl = vl_lane + (uint32_t)kv * 16 * (KSTR * 2);
            #pragma unroll
            for (int jd = 0; jd < 8; jd++) {
                uint32_t bh0, bh1, bl0, bl1;
                ldsm_x2_t(bh0, bh1, rh + jd * 16);
                ldsm_x2_t(bl0, bl1, rl + jd * 16);
                mma_bf16(O[jd], ah, bh0, bh1);
                mma_bf16(O[jd], ah, bl0, bl1);
                mma_bf16(O[jd], al, bh0, bh1);
            }
        }
    }

    // epilogue: write bf16 hi/lo planes directly
    float inv0 = 1.f / l0, inv1 = 1.f / l1;
    const size_t r0 = (size_t)b * TT + tq0;
    const size_t r1 = r0 + 8;
    #pragma unroll
    for (int jd = 0; jd < 8; jd++) {
        int col = h * DH + 8 * jd + 2 * t;
        uint32_t hA, lA, hB, lB;
        split2_bf16(O[jd][0] * inv0, O[jd][1] * inv0, hA, lA);
        split2_bf16(O[jd][2] * inv1, O[jd][3] * inv1, hB, lB);
        *(uint32_t*)&outh[r0 * (HH * DH) + col] = hA;
        *(uint32_t*)&outl[r0 * (HH * DH) + col] = lA;
        *(uint32_t*)&outh[r1 * (HH * DH) + col] = hB;
        *(uint32_t*)&outl[r1 * (HH * DH) + col] = lB;
    }
}

// ---------------------------------------------------------------------------
extern "C" void kernel_launch(void* const* d_in, const int* in_sizes, int n_in,
                              void* d_out, int out_size)
{
    const float* query   = (const float*)d_in[0];
    const float* key_    = (const float*)d_in[1];
    const float* value   = (const float*)d_in[2];
    const float* Wq      = (const float*)d_in[3];
    const float* bq      = (const float*)d_in[4];
    const float* Wk      = (const float*)d_in[5];
    const float* bk      = (const float*)d_in[6];
    const float* Wv      = (const float*)d_in[7];
    const float* bv      = (const float*)d_in[8];
    const float* Wo      = (const float*)d_in[9];
    const float* bo      = (const float*)d_in[10];
    const float* cbias   = (const float*)d_in[11];
    const float* rbias   = (const float*)d_in[12];
    const float* pos_emb = (const float*)d_in[13];

    float *q, *k, *v, *pk;
    cudaGetSymbolAddress((void**)&q, g_q);
    cudaGetSymbolAddress((void**)&k, g_k);
    cudaGetSymbolAddress((void**)&v, g_v);
    cudaGetSymbolAddress((void**)&pk, g_pk);

    __nv_bfloat16 *wqh, *wql, *wkh, *wkl, *wvh, *wvl, *woh, *wol;
    __nv_bfloat16 *xh, *xl, *yh, *yl, *zh, *zl, *ath, *atl;
    cudaGetSymbolAddress((void**)&wqh, g_wq_h); cudaGetSymbolAddress((void**)&wql, g_wq_l);
    cudaGetSymbolAddress((void**)&wkh, g_wk_h); cudaGetSymbolAddress((void**)&wkl, g_wk_l);
    cudaGetSymbolAddress((void**)&wvh, g_wv_h); cudaGetSymbolAddress((void**)&wvl, g_wv_l);
    cudaGetSymbolAddress((void**)&woh, g_wo_h); cudaGetSymbolAddress((void**)&wol, g_wo_l);
    cudaGetSymbolAddress((void**)&xh, g_x_h);   cudaGetSymbolAddress((void**)&xl, g_x_l);
    cudaGetSymbolAddress((void**)&yh, g_y_h);   cudaGetSymbolAddress((void**)&yl, g_y_l);
    cudaGetSymbolAddress((void**)&zh, g_z_h);   cudaGetSymbolAddress((void**)&zl, g_z_l);
    cudaGetSymbolAddress((void**)&ath, g_a_h);  cudaGetSymbolAddress((void**)&atl, g_a_l);

    const int M = BB * TT;     // 4096
    const int N = HH * DH;     // 1024
    const int K = DD;          // 1024

    const int wn4 = DD * HH * DH / 4;     // 262144
    const int an4 = BB * TT * DD / 4;     // 1048576
    pack_bf16<<<wn4 / 256, 256>>>(Wq, wqh, wql, wn4);
    pack_bf16<<<wn4 / 256, 256>>>(Wk, wkh, wkl, wn4);
    pack_bf16<<<wn4 / 256, 256>>>(Wv, wvh, wvl, wn4);
    pack_bf16<<<wn4 / 256, 256>>>(Wo, woh, wol, wn4);
    pack_bf16<<<an4 / 256, 256>>>(query, xh, xl, an4);
    pack_bf16<<<an4 / 256, 256>>>(key_,  yh, yl, an4);
    pack_bf16<<<an4 / 256, 256>>>(value, zh, zl, an4);

    cudaFuncSetAttribute(gemm_bf16p2,
                         cudaFuncAttributeMaxDynamicSharedMemorySize, G2_SMEM);
    dim3 gg(N / 128, M / 128);  // (8, 32)
    gemm_bf16p2<<<gg, 256, G2_SMEM>>>(xh, xl, wqh, wql, bq, q, M, N, K);
    gemm_bf16p2<<<gg, 256, G2_SMEM>>>(yh, yl, wkh, wkl, bk, k, M, N, K);
    gemm_bf16p2<<<gg, 256, G2_SMEM>>>(zh, zl, wvh, wvl, bv, v, M, N, K);

    pk_init<<<(NREL * DD + 255) / 256, 256>>>(bk, pk);
    pk_gemm_split<<<dim3(DD / 256, DD / 128), 256>>>(pos_emb, Wk, pk);

    cudaFuncSetAttribute(attn_mma,
                         cudaFuncAttributeMaxDynamicSharedMemorySize, AT_SMEM);
    attn_mma<<<dim3(TT / 64, HH, BB), 128, AT_SMEM>>>(q, k, v, pk,
                                                      cbias, rbias, ath, atl);

    // output projection -> d_out
    gemm_bf16p2<<<gg, 256, G2_SMEM>>>(ath, atl, woh, wol, bo, (float*)d_out, M, N, K);
}

// round 15
// speedup vs baseline: 5.0343x; 1.0607x over previous
#include <cuda_runtime.h>
#include <cuda_bf16.h>
#include <math.h>
#include <stdint.h>

#define BB 2
#define TT 2048
#define DD 1024
#define HH 16
#define DH 64
#define NREL 7

// Scratch (static device globals — no allocation)
__device__ float g_pk[NREL*HH*DH];

// packed bf16 hi/lo planes (W [K][N], acts [M][K], all layout-preserving)
__device__ __nv_bfloat16 g_wq_h[DD*HH*DH], g_wq_l[DD*HH*DH];
__device__ __nv_bfloat16 g_wk_h[DD*HH*DH], g_wk_l[DD*HH*DH];
__device__ __nv_bfloat16 g_wv_h[DD*HH*DH], g_wv_l[DD*HH*DH];
__device__ __nv_bfloat16 g_wo_h[DD*HH*DH], g_wo_l[DD*HH*DH];
__device__ __nv_bfloat16 g_x_h[BB*TT*DD],  g_x_l[BB*TT*DD];   // query in
__device__ __nv_bfloat16 g_y_h[BB*TT*DD],  g_y_l[BB*TT*DD];   // key in
__device__ __nv_bfloat16 g_z_h[BB*TT*DD],  g_z_l[BB*TT*DD];   // value in
__device__ __nv_bfloat16 g_qp_h[BB*TT*DD], g_qp_l[BB*TT*DD];  // q proj planes
__device__ __nv_bfloat16 g_kp_h[BB*TT*DD], g_kp_l[BB*TT*DD];  // k proj planes
__device__ __nv_bfloat16 g_vp_h[BB*TT*DD], g_vp_l[BB*TT*DD];  // v proj planes
__device__ __nv_bfloat16 g_a_h[BB*TT*DD],  g_a_l[BB*TT*DD];   // attn out planes

// ---------------------------------------------------------------------------
// helpers
// ---------------------------------------------------------------------------
__device__ __forceinline__ void cp16s(uint32_t saddr, const void* gmem) {
    asm volatile("cp.async.ca.shared.global [%0], [%1], 16;\n" :: "r"(saddr), "l"(gmem));
}
__device__ __forceinline__ void cp_commit() {
    asm volatile("cp.async.commit_group;\n");
}
__device__ __forceinline__ void cp_wait2() {
    asm volatile("cp.async.wait_group 2;\n");
}
__device__ __forceinline__ void cp_wait1() {
    asm volatile("cp.async.wait_group 1;\n");
}
__device__ __forceinline__ void cp_wait0() {
    asm volatile("cp.async.wait_group 0;\n");
}

__device__ __forceinline__ void mma_bf16(float* c, const uint32_t* a,
                                         uint32_t b0, uint32_t b1) {
    asm volatile(
        "mma.sync.aligned.m16n8k16.row.col.f32.bf16.bf16.f32 "
        "{%0,%1,%2,%3}, {%4,%5,%6,%7}, {%8,%9}, {%0,%1,%2,%3};"
        : "+f"(c[0]), "+f"(c[1]), "+f"(c[2]), "+f"(c[3])
        : "r"(a[0]), "r"(a[1]), "r"(a[2]), "r"(a[3]), "r"(b0), "r"(b1));
}

__device__ __forceinline__ void ldsm_x2_t(uint32_t& r0, uint32_t& r1, uint32_t addr) {
    asm volatile("ldmatrix.sync.aligned.m8n8.x2.trans.shared.b16 {%0,%1}, [%2];"
                 : "=r"(r0), "=r"(r1) : "r"(addr));
}
__device__ __forceinline__ void ldsm_x4(uint32_t* r, uint32_t addr) {
    asm volatile("ldmatrix.sync.aligned.m8n8.x4.shared.b16 {%0,%1,%2,%3}, [%4];"
                 : "=r"(r[0]), "=r"(r[1]), "=r"(r[2]), "=r"(r[3]) : "r"(addr));
}

__device__ __forceinline__ void split2_bf16(float x0, float x1,
                                            uint32_t& hi, uint32_t& lo) {
    __nv_bfloat16 h0 = __float2bfloat16_rn(x0);
    __nv_bfloat16 h1 = __float2bfloat16_rn(x1);
    float r0 = x0 - __bfloat162float(h0);
    float r1 = x1 - __bfloat162float(h1);
    __nv_bfloat162 H = __halves2bfloat162(h0, h1);
    __nv_bfloat162 L = __halves2bfloat162(__float2bfloat16_rn(r0),
                                          __float2bfloat16_rn(r1));
    hi = *(uint32_t*)&H;
    lo = *(uint32_t*)&L;
}

// ---------------------------------------------------------------------------
// pack fp32 -> bf16 hi/lo planes (layout preserved)
// ---------------------------------------------------------------------------
__global__ __launch_bounds__(256) void pack_bf16(
    const float* __restrict__ src, __nv_bfloat16* __restrict__ hi,
    __nv_bfloat16* __restrict__ lo, int n4)
{
    int i = blockIdx.x * 256 + threadIdx.x;
    if (i < n4) {
        float4 v = ((const float4*)src)[i];
        uint32_t h01, l01, h23, l23;
        split2_bf16(v.x, v.y, h01, l01);
        split2_bf16(v.z, v.w, h23, l23);
        ((uint2*)hi)[i] = make_uint2(h01, h23);
        ((uint2*)lo)[i] = make_uint2(l01, l23);
    }
}

// ---------------------------------------------------------------------------
// packed-bf16 3-term mma GEMM: C = A@W + bias.
// BM=128, BN=128, BK=32, 256 threads (8 warps = 4m x 2n), warp tile 32x64.
// If C != null -> fp32 output; else -> bf16 hi/lo plane output (outh/outl).
// ---------------------------------------------------------------------------
#define AP2 40
#define BP2 136
#define A_PLANE2 (128 * AP2 * 2)
#define B_PLANE2 (32 * BP2 * 2)
#define STAGE2   (2 * A_PLANE2 + 2 * B_PLANE2)
#define G2_SMEM  (2 * STAGE2)

__global__ __launch_bounds__(256, 2) void gemm_bf16p2(
    const __nv_bfloat16* __restrict__ Ah_g, const __nv_bfloat16* __restrict__ Al_g,
    const __nv_bfloat16* __restrict__ Bh_g, const __nv_bfloat16* __restrict__ Bl_g,
    const float* __restrict__ bias, float* __restrict__ C,
    __nv_bfloat16* __restrict__ outh, __nv_bfloat16* __restrict__ outl,
    int M, int N, int K)
{
    extern __shared__ char smraw[];
    const uint32_t sb0 = (uint32_t)__cvta_generic_to_shared(smraw);

    const int tid  = threadIdx.x;
    const int warp = tid >> 5;
    const int lane = tid & 31;
    const int t    = lane & 3;
    const int g    = lane >> 2;
    const int lm   = lane & 15;
    const int lq   = lane >> 4;
    const int wm   = (warp & 3) * 32;
    const int wn   = (warp >> 2) * 64;
    const int bm   = blockIdx.y * 128;
    const int bn   = blockIdx.x * 128;
    const int NIT  = K >> 5;

    auto fill = [&](int c, int s) {
        const int k0 = c * 32;
        const uint32_t st = sb0 + s * STAGE2;
        #pragma unroll
        for (int u = 0; u < 8; u++) {
            int id = tid + u * 256;
            int plane = id >> 9;
            int wi = id & 511;
            if (plane < 2) {
                int row = wi >> 2;
                int c8  = (wi & 3) * 8;
                const __nv_bfloat16* src = (plane == 0) ? Ah_g : Al_g;
                uint32_t dst = st + plane * A_PLANE2 +
                               (uint32_t)(row * AP2 + c8) * 2;
                cp16s(dst, src + (size_t)(bm + row) * K + k0 + c8);
            } else {
                int krow = wi >> 4;
                int c8   = (wi & 15) * 8;
                const __nv_bfloat16* src = (plane == 2) ? Bh_g : Bl_g;
                uint32_t dst = st + 2 * A_PLANE2 + (plane - 2) * B_PLANE2 +
                               (uint32_t)(krow * BP2 + c8) * 2;
                cp16s(dst, src + (size_t)(k0 + krow) * N + bn + c8);
            }
        }
        cp_commit();
    };

    fill(0, 0);
    fill(1, 1);

    float acc[2][8][4];
    #pragma unroll
    for (int i = 0; i < 2; i++)
        #pragma unroll
        for (int j = 0; j < 8; j++)
            #pragma unroll
            for (int r = 0; r < 4; r++) acc[i][j][r] = 0.f;

    for (int it = 0; it < NIT; it++) {
        const int s = it & 1;
        if (it + 2 < NIT) cp_wait1(); else cp_wait0();
        __syncthreads();

        const uint32_t st = sb0 + s * STAGE2;
        const uint32_t ah_base = st;
        const uint32_t al_base = st + A_PLANE2;
        const uint32_t bh_base = st + 2 * A_PLANE2;
        const uint32_t bl_base = st + 2 * A_PLANE2 + B_PLANE2;

        #pragma unroll
        for (int ks = 0; ks < 2; ks++) {
            uint32_t ah[2][4], al[2][4];
            #pragma unroll
            for (int i = 0; i < 2; i++) {
                uint32_t off = (uint32_t)((wm + i * 16 + lm) * AP2) * 2 +
                               lq * 16 + ks * 32;
                ldsm_x4(ah[i], ah_base + off);
                ldsm_x4(al[i], al_base + off);
            }
            #pragma unroll
            for (int j = 0; j < 8; j++) {
                uint32_t boff = (uint32_t)((ks * 16 + lm) * BP2) * 2 +
                                (uint32_t)(wn + j * 8) * 2;
                uint32_t bh0, bh1, bl0, bl1;
                ldsm_x2_t(bh0, bh1, bh_base + boff);
                ldsm_x2_t(bl0, bl1, bl_base + boff);
                #pragma unroll
                for (int i = 0; i < 2; i++) {
                    mma_bf16(acc[i][j], ah[i], bh0, bh1);
                    mma_bf16(acc[i][j], ah[i], bl0, bl1);
                    mma_bf16(acc[i][j], al[i], bh0, bh1);
                }
            }
        }
        __syncthreads();
        if (it + 2 < NIT) fill(it + 2, s);
    }

    // epilogue
    #pragma unroll
    for (int j = 0; j < 8; j++) {
        const int col = bn + wn + j * 8 + 2 * t;
        const float bv0 = bias[col];
        const float bv1 = bias[col + 1];
        #pragma unroll
        for (int i = 0; i < 2; i++) {
            const int row0 = bm + wm + i * 16 + g;
            float a0 = acc[i][j][0] + bv0, a1 = acc[i][j][1] + bv1;
            float a2 = acc[i][j][2] + bv0, a3 = acc[i][j][3] + bv1;
            if (C) {
                *(float2*)(C + (size_t)row0 * N + col)       = make_float2(a0, a1);
                *(float2*)(C + (size_t)(row0 + 8) * N + col) = make_float2(a2, a3);
            } else {
                uint32_t h0, l0, h1, l1;
                split2_bf16(a0, a1, h0, l0);
                split2_bf16(a2, a3, h1, l1);
                *(uint32_t*)&outh[(size_t)row0 * N + col]       = h0;
                *(uint32_t*)&outl[(size_t)row0 * N + col]       = l0;
                *(uint32_t*)&outh[(size_t)(row0 + 8) * N + col] = h1;
                *(uint32_t*)&outl[(size_t)(row0 + 8) * N + col] = l1;
            }
        }
    }
}

// ---------------------------------------------------------------------------
// pk path
// ---------------------------------------------------------------------------
__global__ void pk_init(const float* __restrict__ bk, float* __restrict__ pk)
{
    int i = blockIdx.x * 256 + threadIdx.x;
    if (i < NREL * DD) pk[i] = bk[i & (DD - 1)];
}

__global__ __launch_bounds__(256) void pk_gemm_split(
    const float* __restrict__ pos_emb, const float* __restrict__ Wk,
    float* __restrict__ pk)
{
    __shared__ float pe_s[NREL][64];
    const int n  = blockIdx.x * 256 + threadIdx.x;
    const int k0 = blockIdx.y * 64;

    for (int i = threadIdx.x; i < NREL * 64; i += 256) {
        int r = i >> 6, kk = i & 63;
        pe_s[r][kk] = pos_emb[r * DD + k0 + kk];
    }
    __syncthreads();

    float acc[NREL];
    #pragma unroll
    for (int r = 0; r < NREL; r++) acc[r] = 0.f;

    #pragma unroll 4
    for (int kk = 0; kk < 64; kk++) {
        float w = Wk[(size_t)(k0 + kk) * DD + n];
        #pragma unroll
        for (int r = 0; r < NREL; r++) acc[r] += pe_s[r][kk] * w;
    }
    #pragma unroll
    for (int r = 0; r < NREL; r++)
        atomicAdd(&pk[r * DD + n], acc[r]);
}

// ---------------------------------------------------------------------------
// Flash attention, all operands pre-packed bf16 hi/lo planes.
// cp.async tile loads (no conversion); content bias via per-key uk = u . k.
// ---------------------------------------------------------------------------
#define KSTR 72
#define TILE_B (64 * KSTR * 2)      // 9216

#define ATQ_H    0
#define ATQ_L    TILE_B
#define ATKV     (2 * TILE_B)       // 18432
#define KV_STAGE (4 * TILE_B)       // 36864
#define SMALL_OFF (ATKV + 2 * KV_STAGE)        // 92160
#define PKS_OFF  (SMALL_OFF + 64*8*4)
#define US_OFF   (PKS_OFF + NREL*64*4)
#define UK_OFF   (US_OFF + 64*4)
#define CORR_OFF (UK_OFF + 64*4)
#define AT_SMEM  (CORR_OFF + 32)

__global__ __launch_bounds__(128, 2) void attn_mma(
    const __nv_bfloat16* __restrict__ qph, const __nv_bfloat16* __restrict__ qpl,
    const __nv_bfloat16* __restrict__ kph, const __nv_bfloat16* __restrict__ kpl,
    const __nv_bfloat16* __restrict__ vph, const __nv_bfloat16* __restrict__ vpl,
    const float* __restrict__ pk,
    const float* __restrict__ cbias, const float* __restrict__ rbias,
    __nv_bfloat16* __restrict__ outh, __nv_bfloat16* __restrict__ outl)
{
    extern __shared__ char smraw[];
    const uint32_t smb = (uint32_t)__cvta_generic_to_shared(smraw);
    __nv_bfloat16* Qh = (__nv_bfloat16*)(smraw + ATQ_H);
    __nv_bfloat16* Ql = (__nv_bfloat16*)(smraw + ATQ_L);
    float* smalls = (float*)(smraw + SMALL_OFF);
    float* pks    = (float*)(smraw + PKS_OFF);
    float* us     = (float*)(smraw + US_OFF);
    float* uk     = (float*)(smraw + UK_OFF);
    float* corr   = (float*)(smraw + CORR_OFF);

    const int tid  = threadIdx.x;
    const int warp = tid >> 5;
    const int lane = tid & 31;
    const int g    = lane >> 2;
    const int t    = lane & 3;
    const int lm   = lane & 15;
    const int wm   = warp * 16;
    const int h    = blockIdx.y;
    const int b    = blockIdx.z;
    const int q0   = blockIdx.x * 64;
    const int NKT  = TT / 64;       // 32

    const size_t hoff = (size_t)h * DH;

    // K/V tile fill via cp.async: 4 planes x 64 rows x 8 units = 16/thread
    auto fillKV = [&](int c, int s) {
        const int kt = c * 64;
        const uint32_t st = smb + ATKV + s * KV_STAGE;
        #pragma unroll
        for (int u = 0; u < 16; u++) {
            int id = tid + u * 128;
            int plane = id >> 9;        // 0:Kh 1:Kl 2:Vh 3:Vl
            int wi = id & 511;
            int row = wi >> 3;
            int unit = wi & 7;
            const __nv_bfloat16* src =
                (plane == 0) ? kph : (plane == 1) ? kpl :
                (plane == 2) ? vph : vpl;
            uint32_t dst = st + plane * TILE_B +
                           (uint32_t)(row * (KSTR * 2) + unit * 16);
            cp16s(dst, src + ((size_t)b * TT + kt + row) * (HH * DH) + hoff + unit * 8);
        }
        cp_commit();
    };

    // Q fill (once): 2 planes x 64 rows x 8 units = 8/thread
    #pragma unroll
    for (int u = 0; u < 8; u++) {
        int id = tid + u * 128;
        int plane = id >> 9;
        int wi = id & 511;
        int row = wi >> 3;
        int unit = wi & 7;
        const __nv_bfloat16* src = plane ? qpl : qph;
        uint32_t dst = smb + (plane ? ATQ_L : ATQ_H) +
                       (uint32_t)(row * (KSTR * 2) + unit * 16);
        cp16s(dst, src + ((size_t)b * TT + q0 + row) * (HH * DH) + hoff + unit * 8);
    }
    cp_commit();
    fillKV(0, 0);
    fillKV(1, 1);

    // biases / pk tiles
    if (tid < 64) us[tid] = cbias[h * DH + tid];
    for (int i = tid; i < NREL * 64; i += 128) {
        int r = i >> 6, d = i & 63;
        pks[i] = pk[r * DD + h * DH + d];
    }
    __syncthreads();

    if (tid < NREL) {
        float s = 0.f;
        for (int d = 0; d < 64; d++)
            s += rbias[h * DH + d] * pks[tid * 64 + d];
        corr[tid] = s;
    }

    cp_wait2();          // Q group complete
    __syncthreads();

    // smalls[row][r] = q_row . pk_r + rbias . pk_r
    if (tid < 64) {
        float accr[NREL];
        #pragma unroll
        for (int r = 0; r < NREL; r++) accr[r] = corr[r];
        for (int d = 0; d < 64; d++) {
            float qv = __bfloat162float(Qh[tid * KSTR + d]) +
                       __bfloat162float(Ql[tid * KSTR + d]);
            #pragma unroll
            for (int r = 0; r < NREL; r++) accr[r] += qv * pks[r * 64 + d];
        }
        #pragma unroll
        for (int r = 0; r < NREL; r++) smalls[tid * 8 + r] = accr[r];
    }

    // persistent Q fragments
    uint32_t qfh[4][4], qfl[4][4];
    #pragma unroll
    for (int ks = 0; ks < 4; ks++) {
        int d0 = 16 * ks + 2 * t;
        qfh[ks][0] = *(uint32_t*)&Qh[(wm + g) * KSTR + d0];
        qfh[ks][1] = *(uint32_t*)&Qh[(wm + g + 8) * KSTR + d0];
        qfh[ks][2] = *(uint32_t*)&Qh[(wm + g) * KSTR + d0 + 8];
        qfh[ks][3] = *(uint32_t*)&Qh[(wm + g + 8) * KSTR + d0 + 8];
        qfl[ks][0] = *(uint32_t*)&Ql[(wm + g) * KSTR + d0];
        qfl[ks][1] = *(uint32_t*)&Ql[(wm + g + 8) * KSTR + d0];
        qfl[ks][2] = *(uint32_t*)&Ql[(wm + g) * KSTR + d0 + 8];
        qfl[ks][3] = *(uint32_t*)&Ql[(wm + g + 8) * KSTR + d0 + 8];
    }

    float m0 = -1e30f, m1 = -1e30f, l0 = 0.f, l1 = 0.f;
    float O[8][4];
    #pragma unroll
    for (int jd = 0; jd < 8; jd++)
        #pragma unroll
        for (int r = 0; r < 4; r++) O[jd][r] = 0.f;

    const float scale = 0.125f;
    const int tq0 = q0 + wm + g;
    const int rl0 = wm + g;

    for (int it = 0; it < NKT; it++) {
        const int s = it & 1;
        if (it + 1 < NKT) cp_wait1(); else cp_wait0();
        __syncthreads();

        const uint32_t kvb = smb + ATKV + s * KV_STAGE;
        const __nv_bfloat16* Khs = (__nv_bfloat16*)(smraw + ATKV + s * KV_STAGE);
        const __nv_bfloat16* Kls = Khs + TILE_B / 2;

        // uk[key] = u . (Kh+Kl)[key]; 2 threads per key
        {
            int key = tid >> 1;
            int half = tid & 1;
            float sum = 0.f;
            #pragma unroll
            for (int d2 = 0; d2 < 16; d2++) {
                int d = half * 32 + d2 * 2;
                __nv_bfloat162 a = *(__nv_bfloat162*)&Khs[key * KSTR + d];
                __nv_bfloat162 bl = *(__nv_bfloat162*)&Kls[key * KSTR + d];
                float k0 = __bfloat162float(a.x) + __bfloat162float(bl.x);
                float k1 = __bfloat162float(a.y) + __bfloat162float(bl.y);
                sum += us[d] * k0 + us[d + 1] * k1;
            }
            sum += __shfl_xor_sync(0xffffffffu, sum, 1);
            if (!half) uk[key] = sum;
        }

        // S = q K^T (3-term)
        float S[8][4];
        #pragma unroll
        for (int j = 0; j < 8; j++)
            #pragma unroll
            for (int r = 0; r < 4; r++) S[j][r] = 0.f;

        #pragma unroll
        for (int ks = 0; ks < 4; ks++) {
            const int d0 = 16 * ks + 2 * t;
            #pragma unroll
            for (int j = 0; j < 8; j++) {
                const int key = 8 * j + g;
                uint32_t bh0 = *(uint32_t*)&Khs[key * KSTR + d0];
                uint32_t bh1 = *(uint32_t*)&Khs[key * KSTR + d0 + 8];
                uint32_t bl0 = *(uint32_t*)&Kls[key * KSTR + d0];
                uint32_t bl1 = *(uint32_t*)&Kls[key * KSTR + d0 + 8];
                mma_bf16(S[j], qfh[ks], bh0, bh1);
                mma_bf16(S[j], qfh[ks], bl0, bl1);
                mma_bf16(S[j], qfl[ks], bh0, bh1);
            }
        }

        __syncthreads();          // uk visible to all warps

        // bias + scale + row max
        const int kt = it * 64;
        float mx0 = -1e30f, mx1 = -1e30f;
        #pragma unroll
        for (int j = 0; j < 8; j++) {
            #pragma unroll
            for (int c = 0; c < 2; c++) {
                int kk = 8 * j + 2 * t + c;
                int tk = kt + kk;
                int d0 = min(3, max(-3, tq0 - tk)) + 3;
                int d1 = min(3, max(-3, tq0 + 8 - tk)) + 3;
                float ukv = uk[kk];
                S[j][c]     = (S[j][c]     + ukv + smalls[rl0 * 8 + d0]) * scale;
                S[j][2 + c] = (S[j][2 + c] + ukv + smalls[(rl0 + 8) * 8 + d1]) * scale;
                mx0 = fmaxf(mx0, S[j][c]);
                mx1 = fmaxf(mx1, S[j][2 + c]);
            }
        }
        mx0 = fmaxf(mx0, __shfl_xor_sync(0xffffffffu, mx0, 1));
        mx0 = fmaxf(mx0, __shfl_xor_sync(0xffffffffu, mx0, 2));
        mx1 = fmaxf(mx1, __shfl_xor_sync(0xffffffffu, mx1, 1));
        mx1 = fmaxf(mx1, __shfl_xor_sync(0xffffffffu, mx1, 2));

        float mn0 = fmaxf(m0, mx0), mn1 = fmaxf(m1, mx1);
        float cr0 = __expf(m0 - mn0), cr1 = __expf(m1 - mn1);
        m0 = mn0; m1 = mn1;

        uint32_t phA[8], plA[8], phB[8], plB[8];
        float s0 = 0.f, s1 = 0.f;
        #pragma unroll
        for (int j = 0; j < 8; j++) {
            float p0 = __expf(S[j][0] - mn0);
            float p1 = __expf(S[j][1] - mn0);
            float p2 = __expf(S[j][2] - mn1);
            float p3 = __expf(S[j][3] - mn1);
            s0 += p0 + p1; s1 += p2 + p3;
            split2_bf16(p0, p1, phA[j], plA[j]);
            split2_bf16(p2, p3, phB[j], plB[j]);
        }
        s0 += __shfl_xor_sync(0xffffffffu, s0, 1);
        s0 += __shfl_xor_sync(0xffffffffu, s0, 2);
        s1 += __shfl_xor_sync(0xffffffffu, s1, 1);
        s1 += __shfl_xor_sync(0xffffffffu, s1, 2);
        l0 = l0 * cr0 + s0;
        l1 = l1 * cr1 + s1;

        #pragma unroll
        for (int jd = 0; jd < 8; jd++) {
            O[jd][0] *= cr0; O[jd][1] *= cr0;
            O[jd][2] *= cr1; O[jd][3] *= cr1;
        }

        // O += P V (3-term), V via ldmatrix.trans
        const uint32_t vh_lane = kvb + 2 * TILE_B + (uint32_t)lm * (KSTR * 2);
        const uint32_t vl_lane = kvb + 3 * TILE_B + (uint32_t)lm * (KSTR * 2);
        #pragma unroll
        for (int kv = 0; kv < 4; kv++) {
            uint32_t ah[4] = { phA[2*kv], phB[2*kv], phA[2*kv+1], phB[2*kv+1] };
            uint32_t al[4] = { plA[2*kv], plB[2*kv], plA[2*kv+1], plB[2*kv+1] };
            const uint32_t rh = vh_lane + (uint32_t)kv * 16 * (KSTR * 2);
            const uint32_t rl = vl_lane + (uint32_t)kv * 16 * (KSTR * 2);
            #pragma unroll
            for (int jd = 0; jd < 8; jd++) {
                uint32_t bh0, bh1, bl0, bl1;
                ldsm_x2_t(bh0, bh1, rh + jd * 16);
                ldsm_x2_t(bl0, bl1, rl + jd * 16);
                mma_bf16(O[jd], ah, bh0, bh1);
                mma_bf16(O[jd], ah, bl0, bl1);
                mma_bf16(O[jd], al, bh0, bh1);
            }
        }

        // RACE FIX: all reads of stage s (K via scalar LDS, V via ldmatrix)
        // must complete across the whole CTA before cp.async overwrites it.
        __syncthreads();
        if (it + 2 < NKT) fillKV(it + 2, s);
    }

    // epilogue: write bf16 hi/lo planes
    float inv0 = 1.f / l0, inv1 = 1.f / l1;
    const size_t r0 = (size_t)b * TT + tq0;
    const size_t r1 = r0 + 8;
    #pragma unroll
    for (int jd = 0; jd < 8; jd++) {
        int col = h * DH + 8 * jd + 2 * t;
        uint32_t hA, lA, hB, lB;
        split2_bf16(O[jd][0] * inv0, O[jd][1] * inv0, hA, lA);
        split2_bf16(O[jd][2] * inv1, O[jd][3] * inv1, hB, lB);
        *(uint32_t*)&outh[r0 * (HH * DH) + col] = hA;
        *(uint32_t*)&outl[r0 * (HH * DH) + col] = lA;
        *(uint32_t*)&outh[r1 * (HH * DH) + col] = hB;
        *(uint32_t*)&outl[r1 * (HH * DH) + col] = lB;
    }
}

// ---------------------------------------------------------------------------
extern "C" void kernel_launch(void* const* d_in, const int* in_sizes, int n_in,
                              void* d_out, int out_size)
{
    const float* query   = (const float*)d_in[0];
    const float* key_    = (const float*)d_in[1];
    const float* value   = (const float*)d_in[2];
    const float* Wq      = (const float*)d_in[3];
    const float* bq      = (const float*)d_in[4];
    const float* Wk      = (const float*)d_in[5];
    const float* bk      = (const float*)d_in[6];
    const float* Wv      = (const float*)d_in[7];
    const float* bv      = (const float*)d_in[8];
    const float* Wo      = (const float*)d_in[9];
    const float* bo      = (const float*)d_in[10];
    const float* cbias   = (const float*)d_in[11];
    const float* rbias   = (const float*)d_in[12];
    const float* pos_emb = (const float*)d_in[13];

    float *pk;
    cudaGetSymbolAddress((void**)&pk, g_pk);

    __nv_bfloat16 *wqh, *wql, *wkh, *wkl, *wvh, *wvl, *woh, *wol;
    __nv_bfloat16 *xh, *xl, *yh, *yl, *zh, *zl, *ath, *atl;
    __nv_bfloat16 *qph, *qpl, *kp_h, *kp_l, *vp_h, *vp_l;
    cudaGetSymbolAddress((void**)&wqh, g_wq_h); cudaGetSymbolAddress((void**)&wql, g_wq_l);
    cudaGetSymbolAddress((void**)&wkh, g_wk_h); cudaGetSymbolAddress((void**)&wkl, g_wk_l);
    cudaGetSymbolAddress((void**)&wvh, g_wv_h); cudaGetSymbolAddress((void**)&wvl, g_wv_l);
    cudaGetSymbolAddress((void**)&woh, g_wo_h); cudaGetSymbolAddress((void**)&wol, g_wo_l);
    cudaGetSymbolAddress((void**)&xh, g_x_h);   cudaGetSymbolAddress((void**)&xl, g_x_l);
    cudaGetSymbolAddress((void**)&yh, g_y_h);   cudaGetSymbolAddress((void**)&yl, g_y_l);
    cudaGetSymbolAddress((void**)&zh, g_z_h);   cudaGetSymbolAddress((void**)&zl, g_z_l);
    cudaGetSymbolAddress((void**)&ath, g_a_h);  cudaGetSymbolAddress((void**)&atl, g_a_l);
    cudaGetSymbolAddress((void**)&qph, g_qp_h); cudaGetSymbolAddress((void**)&qpl, g_qp_l);
    cudaGetSymbolAddress((void**)&kp_h, g_kp_h); cudaGetSymbolAddress((void**)&kp_l, g_kp_l);
    cudaGetSymbolAddress((void**)&vp_h, g_vp_h); cudaGetSymbolAddress((void**)&vp_l, g_vp_l);

    const int M = BB * TT;     // 4096
    const int N = HH * DH;     // 1024
    const int K = DD;          // 1024

    const int wn4 = DD * HH * DH / 4;
    const int an4 = BB * TT * DD / 4;
    pack_bf16<<<wn4 / 256, 256>>>(Wq, wqh, wql, wn4);
    pack_bf16<<<wn4 / 256, 256>>>(Wk, wkh, wkl, wn4);
    pack_bf16<<<wn4 / 256, 256>>>(Wv, wvh, wvl, wn4);
    pack_bf16<<<wn4 / 256, 256>>>(Wo, woh, wol, wn4);
    pack_bf16<<<an4 / 256, 256>>>(query, xh, xl, an4);
    pack_bf16<<<an4 / 256, 256>>>(key_,  yh, yl, an4);
    pack_bf16<<<an4 / 256, 256>>>(value, zh, zl, an4);

    cudaFuncSetAttribute(gemm_bf16p2,
                         cudaFuncAttributeMaxDynamicSharedMemorySize, G2_SMEM);
    dim3 gg(N / 128, M / 128);  // (8, 32)
    gemm_bf16p2<<<gg, 256, G2_SMEM>>>(xh, xl, wqh, wql, bq,
                                      nullptr, qph, qpl, M, N, K);
    gemm_bf16p2<<<gg, 256, G2_SMEM>>>(yh, yl, wkh, wkl, bk,
                                      nullptr, kp_h, kp_l, M, N, K);
    gemm_bf16p2<<<gg, 256, G2_SMEM>>>(zh, zl, wvh, wvl, bv,
                                      nullptr, vp_h, vp_l, M, N, K);

    pk_init<<<(NREL * DD + 255) / 256, 256>>>(bk, pk);
    pk_gemm_split<<<dim3(DD / 256, DD / 64), 256>>>(pos_emb, Wk, pk);

    cudaFuncSetAttribute(attn_mma,
                         cudaFuncAttributeMaxDynamicSharedMemorySize, AT_SMEM);
    attn_mma<<<dim3(TT / 64, HH, BB), 128, AT_SMEM>>>(
        qph, qpl, kp_h, kp_l, vp_h, vp_l, pk, cbias, rbias, ath, atl);

    // output projection -> d_out
    gemm_bf16p2<<<gg, 256, G2_SMEM>>>(ath, atl, woh, wol, bo,
                                      (float*)d_out, nullptr, nullptr, M, N, K);
}